// round 1
// baseline (speedup 1.0000x reference)
#include <cuda_runtime.h>
#include <cstdint>
#include <cstddef>

#define NN 4096
#define CC 128
#define BB 4
#define NEGV (-9e15f)

// ---------------- scratch (device globals: no allocation allowed) -----------
__device__ float g_h[(size_t)BB * CC * NN];                  // 8 MB  current hidden
__device__ float g_y[(size_t)BB * CC * NN];                  // 8 MB  gemm output / pre-BN
__device__ float g_q[(size_t)BB * 32 * NN];                  // 2 MB  q (=k)
__device__ float g_xv[(size_t)BB * CC * NN];                 // 8 MB  value projection
__device__ float g_xr[(size_t)BB * CC * NN];                 // 8 MB  attention output
__device__ float g_attn[(size_t)BB * NN * NN];               // 256 MB attention matrix
__device__ float g_colpart[(size_t)8 * BB * NN];             // split-n partial column sums
__device__ float g_colinv[(size_t)BB * NN];                  // 1/(1e-9+colsum)
__device__ float g_scale[CC];                                // fused BN scale
__device__ float g_shift[CC];                                // fused BN shift

// ---------------- helpers ----------------------------------------------------
__device__ __forceinline__ float warp_red_sum(float v) {
#pragma unroll
    for (int o = 16; o > 0; o >>= 1) v += __shfl_xor_sync(0xffffffffu, v, o);
    return v;
}
__device__ __forceinline__ float warp_red_max(float v) {
#pragma unroll
    for (int o = 16; o > 0; o >>= 1) v = fmaxf(v, __shfl_xor_sync(0xffffffffu, v, o));
    return v;
}

__device__ __forceinline__ void fma44(float acc[4][4], float4 w, float4 x) {
    acc[0][0] += w.x * x.x; acc[0][1] += w.x * x.y; acc[0][2] += w.x * x.z; acc[0][3] += w.x * x.w;
    acc[1][0] += w.y * x.x; acc[1][1] += w.y * x.y; acc[1][2] += w.y * x.z; acc[1][3] += w.y * x.w;
    acc[2][0] += w.z * x.x; acc[2][1] += w.z * x.y; acc[2][2] += w.z * x.z; acc[2][3] += w.z * x.w;
    acc[3][0] += w.w * x.x; acc[3][1] += w.w * x.y; acc[3][2] += w.w * x.z; acc[3][3] += w.w * x.w;
}

// ---------------- small GEMM: Y[b,o,n] = sum_c W[o,c] * (X1-X2)[b,c,n] + bias --
// Tile BO x BN, 256 threads, each thread 4x4 outputs. K=128 in two 64-chunks.
template <int BO, int BN>
__global__ __launch_bounds__(256) void gemm_small(
    const float* __restrict__ W, const float* __restrict__ X1,
    const float* __restrict__ X2, const float* __restrict__ bias,
    float* __restrict__ Y)
{
    constexpr int TN = BN / 4;
    __shared__ float Ws[CC][BO];      // W transposed: Ws[c][o]
    __shared__ float Xs[64][BN];      // k-chunk of X

    const int b  = blockIdx.z;
    const int n0 = blockIdx.x * BN;
    const int o0 = blockIdx.y * BO;
    const int tid = threadIdx.x;
    const int Otot = BO * gridDim.y;

    for (int idx = tid; idx < BO * CC; idx += 256) {
        int o = idx / CC, c = idx % CC;
        Ws[c][o] = W[(size_t)(o0 + o) * CC + c];
    }

    const float* x1 = X1 + (size_t)b * CC * NN;
    const float* x2 = X2 ? X2 + (size_t)b * CC * NN : nullptr;

    float acc[4][4] = {};
    const int to = tid / TN, tn = tid % TN;

    for (int c0 = 0; c0 < CC; c0 += 64) {
        __syncthreads();
        for (int idx = tid; idx < 64 * BN; idx += 256) {
            int c = idx / BN, n = idx % BN;
            float v = x1[(size_t)(c0 + c) * NN + n0 + n];
            if (x2) v -= x2[(size_t)(c0 + c) * NN + n0 + n];
            Xs[c][n] = v;
        }
        __syncthreads();
#pragma unroll 8
        for (int c = 0; c < 64; c++) {
            float4 w = *(const float4*)&Ws[c0 + c][to * 4];
            float4 x = *(const float4*)&Xs[c][tn * 4];
            fma44(acc, w, x);
        }
    }

#pragma unroll
    for (int i = 0; i < 4; i++) {
        int o = o0 + to * 4 + i;
        float bi = bias ? bias[o] : 0.f;
        float4 r = make_float4(acc[i][0] + bi, acc[i][1] + bi, acc[i][2] + bi, acc[i][3] + bi);
        *(float4*)&Y[((size_t)b * Otot + o) * NN + n0 + tn * 4] = r;
    }
}

// ---------------- energy: E[b,n,m] = sum_{o<32} Q[b,o,n]*Q[b,o,m] ------------
__global__ __launch_bounds__(256) void energy_kernel(
    const float* __restrict__ Q, float* __restrict__ E)
{
    __shared__ float Qn[32][64];
    __shared__ float Qm[32][64];
    const int b = blockIdx.z;
    const int n0 = blockIdx.y * 64, m0 = blockIdx.x * 64;
    const float* q = Q + (size_t)b * 32 * NN;
    const int tid = threadIdx.x;

    for (int idx = tid; idx < 32 * 64; idx += 256) {
        int o = idx / 64, j = idx % 64;
        Qn[o][j] = q[(size_t)o * NN + n0 + j];
        Qm[o][j] = q[(size_t)o * NN + m0 + j];
    }
    __syncthreads();

    const int to = tid / 16, tm = tid % 16;
    float acc[4][4] = {};
#pragma unroll
    for (int o = 0; o < 32; o++) {
        float4 a = *(const float4*)&Qn[o][to * 4];
        float4 c = *(const float4*)&Qm[o][tm * 4];
        fma44(acc, a, c);
    }
#pragma unroll
    for (int i = 0; i < 4; i++) {
        float4 r = make_float4(acc[i][0], acc[i][1], acc[i][2], acc[i][3]);
        *(float4*)&E[((size_t)b * NN + n0 + to * 4 + i) * NN + m0 + tm * 4] = r;
    }
}

// ---------------- masked row softmax, in place -------------------------------
__global__ __launch_bounds__(256) void softmax_kernel(
    float* __restrict__ E, const int* __restrict__ mask)
{
    const int b = blockIdx.y, n = blockIdx.x;
    float* row = E + ((size_t)b * NN + n) * NN;
    const int* mrow = mask + (size_t)b * NN;
    const int tid = threadIdx.x;
    const int rm = mrow[n];

    float vals[16];
    float vmax = -3.4e38f;
#pragma unroll
    for (int k = 0; k < 4; k++) {
        int j = k * 1024 + tid * 4;
        float4 e = *(const float4*)&row[j];
        int4 mm = *(const int4*)&mrow[j];
        vals[k * 4 + 0] = (rm && mm.x) ? e.x : NEGV;
        vals[k * 4 + 1] = (rm && mm.y) ? e.y : NEGV;
        vals[k * 4 + 2] = (rm && mm.z) ? e.z : NEGV;
        vals[k * 4 + 3] = (rm && mm.w) ? e.w : NEGV;
        vmax = fmaxf(vmax, fmaxf(fmaxf(vals[k*4+0], vals[k*4+1]), fmaxf(vals[k*4+2], vals[k*4+3])));
    }

    __shared__ float rmx[8], rsm[8];
    float wm = warp_red_max(vmax);
    if ((tid & 31) == 0) rmx[tid >> 5] = wm;
    __syncthreads();
    float m8 = rmx[0];
#pragma unroll
    for (int i = 1; i < 8; i++) m8 = fmaxf(m8, rmx[i]);

    float s = 0.f;
#pragma unroll
    for (int i = 0; i < 16; i++) { vals[i] = __expf(vals[i] - m8); s += vals[i]; }
    float ws = warp_red_sum(s);
    if ((tid & 31) == 0) rsm[tid >> 5] = ws;
    __syncthreads();
    float tot = 0.f;
#pragma unroll
    for (int i = 0; i < 8; i++) tot += rsm[i];
    float inv = 1.f / tot;

#pragma unroll
    for (int k = 0; k < 4; k++) {
        int j = k * 1024 + tid * 4;
        float4 r = make_float4(vals[k*4+0]*inv, vals[k*4+1]*inv, vals[k*4+2]*inv, vals[k*4+3]*inv);
        *(float4*)&row[j] = r;
    }
}

// ---------------- column-sum (split over n for parallelism) ------------------
__global__ __launch_bounds__(256) void colpart_kernel(const float* __restrict__ A)
{
    const int b = blockIdx.z;
    const int split = blockIdx.y;                 // 0..7, each covers 512 n
    const int m = blockIdx.x * 256 + threadIdx.x;
    const float* a = A + (size_t)b * NN * NN + m;
    const int nbeg = split * 512;
    float s0 = 0.f, s1 = 0.f, s2 = 0.f, s3 = 0.f;
#pragma unroll 2
    for (int n = nbeg; n < nbeg + 512; n += 4) {
        s0 += a[(size_t)(n + 0) * NN];
        s1 += a[(size_t)(n + 1) * NN];
        s2 += a[(size_t)(n + 2) * NN];
        s3 += a[(size_t)(n + 3) * NN];
    }
    g_colpart[((size_t)split * BB + b) * NN + m] = (s0 + s1) + (s2 + s3);
}

__global__ __launch_bounds__(256) void colfin_kernel()
{
    const int b = blockIdx.y;
    const int m = blockIdx.x * 256 + threadIdx.x;
    float s = 0.f;
#pragma unroll
    for (int split = 0; split < 8; split++)
        s += g_colpart[((size_t)split * BB + b) * NN + m];
    g_colinv[(size_t)b * NN + m] = 1.f / (1e-9f + s);
}

// ---------------- attn apply: XR[b,c,m] = (sum_n XV[b,c,n]*A[b,n,m]) * colinv[m]
// Tile 64c x 64m, K-chunks of 32, 256 threads, 4x4 per thread.
__global__ __launch_bounds__(256) void apply_kernel(
    const float* __restrict__ XV, const float* __restrict__ A,
    float* __restrict__ XR)
{
    __shared__ float Xs[32][68];   // [k][c], padded: 68*4 = 272 B (16B multiple)
    __shared__ float As[32][68];   // [k][m]
    const int b = blockIdx.z;
    const int c0 = blockIdx.y * 64;
    const int m0 = blockIdx.x * 64;
    const float* xv = XV + (size_t)b * CC * NN;
    const float* a  = A + (size_t)b * NN * NN;
    const int tid = threadIdx.x;
    const int tc = tid / 16, tm = tid % 16;

    float acc[4][4] = {};
    for (int k0 = 0; k0 < NN; k0 += 32) {
        for (int idx = tid; idx < 64 * 32; idx += 256) {
            int c = idx / 32, k = idx % 32;
            Xs[k][c] = xv[(size_t)(c0 + c) * NN + k0 + k];
        }
        for (int idx = tid; idx < 32 * 64; idx += 256) {
            int k = idx / 64, m = idx % 64;
            As[k][m] = a[(size_t)(k0 + k) * NN + m0 + m];
        }
        __syncthreads();
#pragma unroll
        for (int k = 0; k < 32; k++) {
            float4 xf = *(const float4*)&Xs[k][tc * 4];
            float4 af = *(const float4*)&As[k][tm * 4];
            fma44(acc, xf, af);
        }
        __syncthreads();
    }

    float4 ci = *(const float4*)&g_colinv[(size_t)b * NN + m0 + tm * 4];
#pragma unroll
    for (int i = 0; i < 4; i++) {
        float4 r = make_float4(acc[i][0] * ci.x, acc[i][1] * ci.y, acc[i][2] * ci.z, acc[i][3] * ci.w);
        *(float4*)&XR[((size_t)b * CC + c0 + tc * 4 + i) * NN + m0 + tm * 4] = r;
    }
}

// ---------------- BN stats over (b, n) per channel ----------------------------
__global__ __launch_bounds__(256) void bn_stats_kernel(
    const float* __restrict__ Y, const float* __restrict__ gam, const float* __restrict__ bet)
{
    const int c = blockIdx.x;
    const int tid = threadIdx.x;
    float s = 0.f, s2 = 0.f;
    for (int b = 0; b < BB; b++) {
        const float* p = Y + ((size_t)b * CC + c) * NN;
        for (int n = tid; n < NN; n += 256) {
            float v = p[n];
            s += v; s2 += v * v;
        }
    }
    s = warp_red_sum(s); s2 = warp_red_sum(s2);
    __shared__ float r1[8], r2[8];
    if ((tid & 31) == 0) { r1[tid >> 5] = s; r2[tid >> 5] = s2; }
    __syncthreads();
    if (tid == 0) {
        float ts = 0.f, t2 = 0.f;
#pragma unroll
        for (int i = 0; i < 8; i++) { ts += r1[i]; t2 += r2[i]; }
        const float invN = 1.f / (float)(BB * NN);
        float mean = ts * invN;
        float var  = t2 * invN - mean * mean;
        float sc = gam[c] * rsqrtf(var + 1e-5f);
        g_scale[c] = sc;
        g_shift[c] = bet[c] - mean * sc;
    }
}

// ---------------- BN apply (+relu) [+residual into h and output slab] --------
__global__ __launch_bounds__(256) void bn_apply_kernel(
    const float* __restrict__ Y, float* __restrict__ H,
    float* __restrict__ OUT, int layer)
{
    size_t f = ((size_t)blockIdx.x * 256 + threadIdx.x) * 4;   // over BB*CC*NN
    int n = (int)(f % NN);
    int c = (int)((f / NN) % CC);
    int b = (int)(f / ((size_t)NN * CC));
    float sc = g_scale[c], sh = g_shift[c];
    float4 y = *(const float4*)&Y[f];
    float4 r;
    r.x = fmaxf(fmaf(y.x, sc, sh), 0.f);
    r.y = fmaxf(fmaf(y.y, sc, sh), 0.f);
    r.z = fmaxf(fmaf(y.z, sc, sh), 0.f);
    r.w = fmaxf(fmaf(y.w, sc, sh), 0.f);
    if (OUT) {
        float4 h = *(const float4*)&H[f];
        r.x += h.x; r.y += h.y; r.z += h.z; r.w += h.w;
        *(float4*)&H[f] = r;
        *(float4*)&OUT[(((size_t)b * 4 * CC) + (size_t)layer * CC + c) * NN + n] = r;
    } else {
        *(float4*)&H[f] = r;
    }
}

// ---------------- launch ------------------------------------------------------
extern "C" void kernel_launch(void* const* d_in, const int* in_sizes, int n_in,
                              void* d_out, int out_size)
{
    const float* x    = (const float*)d_in[0];
    const int*   mask = (const int*)  d_in[1];
    const float* w1   = (const float*)d_in[2];
    const float* g1   = (const float*)d_in[3];
    const float* b1   = (const float*)d_in[4];
    const float* w2   = (const float*)d_in[5];
    const float* g2   = (const float*)d_in[6];
    const float* b2   = (const float*)d_in[7];
    const float* wqk  = (const float*)d_in[8];
    const float* wv   = (const float*)d_in[9];
    const float* bv   = (const float*)d_in[10];
    const float* wt   = (const float*)d_in[11];
    const float* bt   = (const float*)d_in[12];
    const float* sg   = (const float*)d_in[13];
    const float* sb   = (const float*)d_in[14];
    float* out = (float*)d_out;

    float *p_h, *p_y, *p_q, *p_xv, *p_xr, *p_attn;
    cudaGetSymbolAddress((void**)&p_h,    g_h);
    cudaGetSymbolAddress((void**)&p_y,    g_y);
    cudaGetSymbolAddress((void**)&p_q,    g_q);
    cudaGetSymbolAddress((void**)&p_xv,   g_xv);
    cudaGetSymbolAddress((void**)&p_xr,   g_xr);
    cudaGetSymbolAddress((void**)&p_attn, g_attn);

    const dim3 blk(256);
    const dim3 grid_g64(NN / 64, 2, BB);     // O=128 GEMMs
    const dim3 grid_g32(NN / 128, 1, BB);    // O=32 GEMM (wqk)
    const dim3 grid_e(NN / 64, NN / 64, BB);
    const dim3 grid_sm(NN, BB);
    const dim3 grid_cp(NN / 256, 8, BB);
    const dim3 grid_cf(NN / 256, BB);
    const dim3 grid_ap(NN / 64, 2, BB);
    const dim3 grid_bn(CC);
    const dim3 grid_ba((unsigned)(((size_t)BB * CC * NN / 4) / 256));

    // head: two conv+BN+relu
    gemm_small<64, 64><<<grid_g64, blk>>>(w1, x, nullptr, nullptr, p_y);
    bn_stats_kernel<<<grid_bn, blk>>>(p_y, g1, b1);
    bn_apply_kernel<<<grid_ba, blk>>>(p_y, p_h, nullptr, 0);

    gemm_small<64, 64><<<grid_g64, blk>>>(w2, p_h, nullptr, nullptr, p_y);
    bn_stats_kernel<<<grid_bn, blk>>>(p_y, g2, b2);
    bn_apply_kernel<<<grid_ba, blk>>>(p_y, p_h, nullptr, 0);

    // 4 offset-attention layers
    for (int i = 0; i < 4; i++) {
        gemm_small<32, 128><<<grid_g32, blk>>>(wqk + (size_t)i * 32 * CC, p_h, nullptr, nullptr, p_q);
        energy_kernel<<<grid_e, blk>>>(p_q, p_attn);
        softmax_kernel<<<grid_sm, blk>>>(p_attn, mask);
        colpart_kernel<<<grid_cp, blk>>>(p_attn);
        colfin_kernel<<<grid_cf, blk>>>();
        gemm_small<64, 64><<<grid_g64, blk>>>(wv + (size_t)i * CC * CC, p_h, nullptr, bv + (size_t)i * CC, p_xv);
        apply_kernel<<<grid_ap, blk>>>(p_xv, p_attn, p_xr);
        gemm_small<64, 64><<<grid_g64, blk>>>(wt + (size_t)i * CC * CC, p_h, p_xr, bt + (size_t)i * CC, p_y);
        bn_stats_kernel<<<grid_bn, blk>>>(p_y, sg + (size_t)i * CC, sb + (size_t)i * CC);
        bn_apply_kernel<<<grid_ba, blk>>>(p_y, p_h, out, i);
    }
}

// round 2
// speedup vs baseline: 1.0691x; 1.0691x over previous
#include <cuda_runtime.h>
#include <cstdint>
#include <cstddef>

#define NN 4096
#define CC 128
#define BB 4
#define NEGV (-9e15f)

typedef unsigned long long ull;

// ---------------- scratch (device globals: no allocation allowed) -----------
__device__ float g_h[(size_t)BB * CC * NN];                  // 8 MB  current hidden
__device__ float g_y[(size_t)BB * CC * NN];                  // 8 MB  gemm output / pre-BN
__device__ float g_q[(size_t)BB * 32 * NN];                  // 2 MB  q (=k)
__device__ float g_xv[(size_t)BB * CC * NN];                 // 8 MB  value projection
__device__ float g_xr[(size_t)BB * CC * NN];                 // 8 MB  attention output
__device__ float g_attn[(size_t)BB * NN * NN];               // 256 MB attention matrix
__device__ float g_colpart[(size_t)8 * BB * NN];             // split-n partial column sums
__device__ float g_colinv[(size_t)BB * NN];                  // 1/(1e-9+colsum)
__device__ float g_scale[CC];                                // fused BN scale
__device__ float g_shift[CC];                                // fused BN shift
__device__ float g_bnp1[8][CC];                              // BN partial sums
__device__ float g_bnp2[8][CC];                              // BN partial sumsq

// ---------------- helpers ----------------------------------------------------
__device__ __forceinline__ float warp_red_sum(float v) {
#pragma unroll
    for (int o = 16; o > 0; o >>= 1) v += __shfl_xor_sync(0xffffffffu, v, o);
    return v;
}
__device__ __forceinline__ float warp_red_max(float v) {
#pragma unroll
    for (int o = 16; o > 0; o >>= 1) v = fmaxf(v, __shfl_xor_sync(0xffffffffu, v, o));
    return v;
}

// packed fp32x2 FMA (sm_100+): d = a*b + d, elementwise on two packed floats
__device__ __forceinline__ void fma2(ull& acc, ull a, ull b) {
    asm("fma.rn.f32x2 %0, %1, %2, %0;" : "+l"(acc) : "l"(a), "l"(b));
}
__device__ __forceinline__ ull pack2(float v) {
    ull r;
    unsigned u = __float_as_uint(v);
    asm("mov.b64 %0, {%1, %1};" : "=l"(r) : "r"(u));
    return r;
}
__device__ __forceinline__ float2 unpack2(ull v) {
    unsigned lo, hi;
    asm("mov.b64 {%0, %1}, %2;" : "=r"(lo), "=r"(hi) : "l"(v));
    return make_float2(__uint_as_float(lo), __uint_as_float(hi));
}

__device__ __forceinline__ void fma44(float acc[4][4], float4 w, float4 x) {
    acc[0][0] += w.x * x.x; acc[0][1] += w.x * x.y; acc[0][2] += w.x * x.z; acc[0][3] += w.x * x.w;
    acc[1][0] += w.y * x.x; acc[1][1] += w.y * x.y; acc[1][2] += w.y * x.z; acc[1][3] += w.y * x.w;
    acc[2][0] += w.z * x.x; acc[2][1] += w.z * x.y; acc[2][2] += w.z * x.z; acc[2][3] += w.z * x.w;
    acc[3][0] += w.w * x.x; acc[3][1] += w.w * x.y; acc[3][2] += w.w * x.z; acc[3][3] += w.w * x.w;
}

// ---------------- gemm_small (kept for wqk, O=32) -----------------------------
template <int BO, int BN>
__global__ __launch_bounds__(256) void gemm_small(
    const float* __restrict__ W, const float* __restrict__ X1,
    const float* __restrict__ X2, const float* __restrict__ bias,
    float* __restrict__ Y)
{
    constexpr int TN = BN / 4;
    __shared__ float Ws[CC][BO];
    __shared__ float Xs[64][BN];

    const int b  = blockIdx.z;
    const int n0 = blockIdx.x * BN;
    const int o0 = blockIdx.y * BO;
    const int tid = threadIdx.x;
    const int Otot = BO * gridDim.y;

    for (int idx = tid; idx < BO * CC; idx += 256) {
        int o = idx / CC, c = idx % CC;
        Ws[c][o] = W[(size_t)(o0 + o) * CC + c];
    }

    const float* x1 = X1 + (size_t)b * CC * NN;
    const float* x2 = X2 ? X2 + (size_t)b * CC * NN : nullptr;

    float acc[4][4] = {};
    const int to = tid / TN, tn = tid % TN;

    for (int c0 = 0; c0 < CC; c0 += 64) {
        __syncthreads();
        for (int idx = tid; idx < 64 * BN; idx += 256) {
            int c = idx / BN, n = idx % BN;
            float v = x1[(size_t)(c0 + c) * NN + n0 + n];
            if (x2) v -= x2[(size_t)(c0 + c) * NN + n0 + n];
            Xs[c][n] = v;
        }
        __syncthreads();
#pragma unroll 8
        for (int c = 0; c < 64; c++) {
            float4 w = *(const float4*)&Ws[c0 + c][to * 4];
            float4 x = *(const float4*)&Xs[c][tn * 4];
            fma44(acc, w, x);
        }
    }

#pragma unroll
    for (int i = 0; i < 4; i++) {
        int o = o0 + to * 4 + i;
        float bi = bias ? bias[o] : 0.f;
        float4 r = make_float4(acc[i][0] + bi, acc[i][1] + bi, acc[i][2] + bi, acc[i][3] + bi);
        *(float4*)&Y[((size_t)b * Otot + o) * NN + n0 + tn * 4] = r;
    }
}

// ---------------- gemm128: Y[b,o,n] = sum_c W[o,c]*(X1-X2)[b,c,n] + bias ------
// O=128, tile 128o x 128n, 128 threads, 8x16 per thread via fp32x2.
__global__ __launch_bounds__(128, 2) void gemm128(
    const float* __restrict__ W, const float* __restrict__ X1,
    const float* __restrict__ X2, const float* __restrict__ bias,
    float* __restrict__ Y)
{
    __shared__ float  Ws[32][132];   // [c_local][o]
    __shared__ double Xd[32][66];    // [c_local][n-pairs]

    const int b  = blockIdx.y;
    const int n0 = blockIdx.x * 128;
    const int tid = threadIdx.x;
    const int tm = tid & 7;          // n-pair group
    const int tc = tid >> 3;         // o group (0..15)

    const float* x1 = X1 + (size_t)b * CC * NN;
    const float* x2 = X2 ? X2 + (size_t)b * CC * NN : nullptr;

    ull acc[8][8];
#pragma unroll
    for (int i = 0; i < 8; i++)
#pragma unroll
        for (int j = 0; j < 8; j++) acc[i][j] = 0ull;

    for (int c0 = 0; c0 < CC; c0 += 32) {
        // fill Ws: thread = o row, read 32 c's, scatter-transpose
        {
            const float* wsrc = W + (size_t)tid * CC + c0;
            float4 wv[8];
#pragma unroll
            for (int r = 0; r < 8; r++) wv[r] = *(const float4*)&wsrc[r * 4];
#pragma unroll
            for (int r = 0; r < 8; r++) {
                Ws[r * 4 + 0][tid] = wv[r].x;
                Ws[r * 4 + 1][tid] = wv[r].y;
                Ws[r * 4 + 2][tid] = wv[r].z;
                Ws[r * 4 + 3][tid] = wv[r].w;
            }
        }
        // fill Xd
#pragma unroll
        for (int t = 0; t < 8; t++) {
            int idx = tid + t * 128;
            int c = idx >> 5, q = idx & 31;
            float4 v = *(const float4*)&x1[(size_t)(c0 + c) * NN + n0 + q * 4];
            if (x2) {
                float4 w = *(const float4*)&x2[(size_t)(c0 + c) * NN + n0 + q * 4];
                v.x -= w.x; v.y -= w.y; v.z -= w.z; v.w -= w.w;
            }
            *(double2*)&Xd[c][q * 2] = *(const double2*)&v;
        }
        __syncthreads();
#pragma unroll
        for (int k = 0; k < 32; k++) {
            float4 xa = *(const float4*)&Ws[k][tc * 8];
            float4 xb = *(const float4*)&Ws[k][tc * 8 + 4];
            ull xc[8];
            xc[0] = pack2(xa.x); xc[1] = pack2(xa.y); xc[2] = pack2(xa.z); xc[3] = pack2(xa.w);
            xc[4] = pack2(xb.x); xc[5] = pack2(xb.y); xc[6] = pack2(xb.z); xc[7] = pack2(xb.w);
            ull af[8];
#pragma unroll
            for (int j = 0; j < 8; j++) af[j] = *(const ull*)&Xd[k][tm + 8 * j];
#pragma unroll
            for (int i = 0; i < 8; i++)
#pragma unroll
                for (int j = 0; j < 8; j++) fma2(acc[i][j], xc[i], af[j]);
        }
        __syncthreads();
    }

#pragma unroll
    for (int i = 0; i < 8; i++) {
        int o = tc * 8 + i;
        float bi = bias ? bias[o] : 0.f;
#pragma unroll
        for (int j = 0; j < 8; j++) {
            float2 r = unpack2(acc[i][j]);
            r.x += bi; r.y += bi;
            *(float2*)&Y[((size_t)b * CC + o) * NN + n0 + 2 * tm + 16 * j] = r;
        }
    }
}

// ---------------- energy: E[b,n,m] = sum_{o<32} Q[b,o,n]*Q[b,o,m] -------------
// tile 128n x 128m, 128 threads, 8x16 per thread, fp32x2.
__global__ __launch_bounds__(128, 2) void energy_kernel(
    const float* __restrict__ Q, float* __restrict__ E)
{
    __shared__ float  Ns[32][132];   // [o][n]
    __shared__ double Md[32][66];    // [o][m-pairs]

    const int b  = blockIdx.z;
    const int n0 = blockIdx.y * 128;
    const int m0 = blockIdx.x * 128;
    const int tid = threadIdx.x;
    const int tm = tid & 7, tc = tid >> 3;
    const float* q = Q + (size_t)b * 32 * NN;

#pragma unroll
    for (int t = 0; t < 8; t++) {
        int idx = tid + t * 128;
        int o = idx >> 5, qd = idx & 31;
        float4 vn = *(const float4*)&q[(size_t)o * NN + n0 + qd * 4];
        *(float4*)&Ns[o][qd * 4] = vn;
        float4 vm = *(const float4*)&q[(size_t)o * NN + m0 + qd * 4];
        *(double2*)&Md[o][qd * 2] = *(const double2*)&vm;
    }
    __syncthreads();

    ull acc[8][8];
#pragma unroll
    for (int i = 0; i < 8; i++)
#pragma unroll
        for (int j = 0; j < 8; j++) acc[i][j] = 0ull;

#pragma unroll
    for (int k = 0; k < 32; k++) {
        float4 xa = *(const float4*)&Ns[k][tc * 8];
        float4 xb = *(const float4*)&Ns[k][tc * 8 + 4];
        ull xc[8];
        xc[0] = pack2(xa.x); xc[1] = pack2(xa.y); xc[2] = pack2(xa.z); xc[3] = pack2(xa.w);
        xc[4] = pack2(xb.x); xc[5] = pack2(xb.y); xc[6] = pack2(xb.z); xc[7] = pack2(xb.w);
        ull af[8];
#pragma unroll
        for (int j = 0; j < 8; j++) af[j] = *(const ull*)&Md[k][tm + 8 * j];
#pragma unroll
        for (int i = 0; i < 8; i++)
#pragma unroll
            for (int j = 0; j < 8; j++) fma2(acc[i][j], xc[i], af[j]);
    }

#pragma unroll
    for (int i = 0; i < 8; i++) {
        size_t row = (size_t)b * NN + n0 + tc * 8 + i;
#pragma unroll
        for (int j = 0; j < 8; j++) {
            float2 r = unpack2(acc[i][j]);
            *(float2*)&E[row * NN + m0 + 2 * tm + 16 * j] = r;
        }
    }
}

// ---------------- masked row softmax, in place --------------------------------
__global__ __launch_bounds__(256) void softmax_kernel(
    float* __restrict__ E, const int* __restrict__ mask)
{
    const int b = blockIdx.y, n = blockIdx.x;
    float* row = E + ((size_t)b * NN + n) * NN;
    const int* mrow = mask + (size_t)b * NN;
    const int tid = threadIdx.x;
    const int rm = mrow[n];

    float vals[16];
    float vmax = -3.4e38f;
#pragma unroll
    for (int k = 0; k < 4; k++) {
        int j = k * 1024 + tid * 4;
        float4 e = *(const float4*)&row[j];
        int4 mm = *(const int4*)&mrow[j];
        vals[k * 4 + 0] = (rm && mm.x) ? e.x : NEGV;
        vals[k * 4 + 1] = (rm && mm.y) ? e.y : NEGV;
        vals[k * 4 + 2] = (rm && mm.z) ? e.z : NEGV;
        vals[k * 4 + 3] = (rm && mm.w) ? e.w : NEGV;
        vmax = fmaxf(vmax, fmaxf(fmaxf(vals[k*4+0], vals[k*4+1]), fmaxf(vals[k*4+2], vals[k*4+3])));
    }

    __shared__ float rmx[8], rsm[8];
    float wm = warp_red_max(vmax);
    if ((tid & 31) == 0) rmx[tid >> 5] = wm;
    __syncthreads();
    float m8 = rmx[0];
#pragma unroll
    for (int i = 1; i < 8; i++) m8 = fmaxf(m8, rmx[i]);

    float s = 0.f;
#pragma unroll
    for (int i = 0; i < 16; i++) { vals[i] = __expf(vals[i] - m8); s += vals[i]; }
    float ws = warp_red_sum(s);
    if ((tid & 31) == 0) rsm[tid >> 5] = ws;
    __syncthreads();
    float tot = 0.f;
#pragma unroll
    for (int i = 0; i < 8; i++) tot += rsm[i];
    float inv = 1.f / tot;

#pragma unroll
    for (int k = 0; k < 4; k++) {
        int j = k * 1024 + tid * 4;
        float4 r = make_float4(vals[k*4+0]*inv, vals[k*4+1]*inv, vals[k*4+2]*inv, vals[k*4+3]*inv);
        *(float4*)&row[j] = r;
    }
}

// ---------------- column-sum (split over n) -----------------------------------
__global__ __launch_bounds__(256) void colpart_kernel(const float* __restrict__ A)
{
    const int b = blockIdx.z;
    const int split = blockIdx.y;
    const int m = blockIdx.x * 256 + threadIdx.x;
    const float* a = A + (size_t)b * NN * NN + m;
    const int nbeg = split * 512;
    float s0 = 0.f, s1 = 0.f, s2 = 0.f, s3 = 0.f;
#pragma unroll 2
    for (int n = nbeg; n < nbeg + 512; n += 4) {
        s0 += a[(size_t)(n + 0) * NN];
        s1 += a[(size_t)(n + 1) * NN];
        s2 += a[(size_t)(n + 2) * NN];
        s3 += a[(size_t)(n + 3) * NN];
    }
    g_colpart[((size_t)split * BB + b) * NN + m] = (s0 + s1) + (s2 + s3);
}

__global__ __launch_bounds__(256) void colfin_kernel()
{
    const int b = blockIdx.y;
    const int m = blockIdx.x * 256 + threadIdx.x;
    float s = 0.f;
#pragma unroll
    for (int split = 0; split < 8; split++)
        s += g_colpart[((size_t)split * BB + b) * NN + m];
    g_colinv[(size_t)b * NN + m] = 1.f / (1e-9f + s);
}

// ---------------- attn apply: XR[b,c,m] = (sum_n XV[b,c,n]*A[b,n,m])*colinv[m] -
// tile 128c x 128m, 128 threads, 8x16 per thread, fp32x2.
__global__ __launch_bounds__(128, 2) void apply_kernel(
    const float* __restrict__ XV, const float* __restrict__ A,
    float* __restrict__ XR)
{
    __shared__ float  Xs[32][132];   // [k][c]
    __shared__ double Ad[32][66];    // [k][m-pairs]

    const int b  = blockIdx.y;
    const int m0 = blockIdx.x * 128;
    const int tid = threadIdx.x;
    const int tm = tid & 7, tc = tid >> 3;
    const float* xv = XV + (size_t)b * CC * NN;
    const float* a  = A + (size_t)b * NN * NN;

    ull acc[8][8];
#pragma unroll
    for (int i = 0; i < 8; i++)
#pragma unroll
        for (int j = 0; j < 8; j++) acc[i][j] = 0ull;

    for (int k0 = 0; k0 < NN; k0 += 32) {
        // fill Xs: thread = c row (xv is [c][k], k contiguous)
        {
            const float* src = xv + (size_t)tid * NN + k0;
            float4 v[8];
#pragma unroll
            for (int r = 0; r < 8; r++) v[r] = *(const float4*)&src[r * 4];
#pragma unroll
            for (int r = 0; r < 8; r++) {
                Xs[r * 4 + 0][tid] = v[r].x;
                Xs[r * 4 + 1][tid] = v[r].y;
                Xs[r * 4 + 2][tid] = v[r].z;
                Xs[r * 4 + 3][tid] = v[r].w;
            }
        }
        // fill Ad: A rows contiguous in m
#pragma unroll
        for (int t = 0; t < 8; t++) {
            int idx = tid + t * 128;
            int k = idx >> 5, q = idx & 31;
            float4 v = *(const float4*)&a[(size_t)(k0 + k) * NN + m0 + q * 4];
            *(double2*)&Ad[k][q * 2] = *(const double2*)&v;
        }
        __syncthreads();
#pragma unroll
        for (int k = 0; k < 32; k++) {
            float4 xa = *(const float4*)&Xs[k][tc * 8];
            float4 xb = *(const float4*)&Xs[k][tc * 8 + 4];
            ull xc[8];
            xc[0] = pack2(xa.x); xc[1] = pack2(xa.y); xc[2] = pack2(xa.z); xc[3] = pack2(xa.w);
            xc[4] = pack2(xb.x); xc[5] = pack2(xb.y); xc[6] = pack2(xb.z); xc[7] = pack2(xb.w);
            ull af[8];
#pragma unroll
            for (int j = 0; j < 8; j++) af[j] = *(const ull*)&Ad[k][tm + 8 * j];
#pragma unroll
            for (int i = 0; i < 8; i++)
#pragma unroll
                for (int j = 0; j < 8; j++) fma2(acc[i][j], xc[i], af[j]);
        }
        __syncthreads();
    }

    const float* cinv = g_colinv + (size_t)b * NN + m0;
#pragma unroll
    for (int j = 0; j < 8; j++) {
        int ml = 2 * tm + 16 * j;
        float2 ci = *(const float2*)&cinv[ml];
#pragma unroll
        for (int i = 0; i < 8; i++) {
            float2 r = unpack2(acc[i][j]);
            r.x *= ci.x; r.y *= ci.y;
            *(float2*)&XR[((size_t)b * CC + tc * 8 + i) * NN + m0 + ml] = r;
        }
    }
}

// ---------------- BN stats: 8-way partials + finalize --------------------------
__global__ __launch_bounds__(256) void bn_part_kernel(const float* __restrict__ Y)
{
    const int c = blockIdx.x;
    const int s = blockIdx.y;                  // 0..7
    const int b = s >> 1;
    const int n0 = (s & 1) * 2048;
    const float* p = Y + ((size_t)b * CC + c) * NN + n0;
    const int tid = threadIdx.x;
    float sum = 0.f, sq = 0.f;
#pragma unroll
    for (int i = 0; i < 8; i++) {
        float v = p[tid + i * 256];
        sum += v; sq += v * v;
    }
    sum = warp_red_sum(sum); sq = warp_red_sum(sq);
    __shared__ float r1[8], r2[8];
    if ((tid & 31) == 0) { r1[tid >> 5] = sum; r2[tid >> 5] = sq; }
    __syncthreads();
    if (tid == 0) {
        float ts = 0.f, t2 = 0.f;
#pragma unroll
        for (int i = 0; i < 8; i++) { ts += r1[i]; t2 += r2[i]; }
        g_bnp1[s][c] = ts;
        g_bnp2[s][c] = t2;
    }
}

__global__ void bn_finalize_kernel(const float* __restrict__ gam, const float* __restrict__ bet)
{
    const int c = threadIdx.x;
    float ts = 0.f, t2 = 0.f;
#pragma unroll
    for (int s = 0; s < 8; s++) { ts += g_bnp1[s][c]; t2 += g_bnp2[s][c]; }
    const float invN = 1.f / (float)(BB * NN);
    float mean = ts * invN;
    float var  = t2 * invN - mean * mean;
    float sc = gam[c] * rsqrtf(var + 1e-5f);
    g_scale[c] = sc;
    g_shift[c] = bet[c] - mean * sc;
}

// ---------------- BN apply (+relu) [+residual into h and output slab] ----------
__global__ __launch_bounds__(256) void bn_apply_kernel(
    const float* __restrict__ Y, float* __restrict__ H,
    float* __restrict__ OUT, int layer)
{
    size_t f = ((size_t)blockIdx.x * 256 + threadIdx.x) * 4;
    int n = (int)(f % NN);
    int c = (int)((f / NN) % CC);
    int b = (int)(f / ((size_t)NN * CC));
    float sc = g_scale[c], sh = g_shift[c];
    float4 y = *(const float4*)&Y[f];
    float4 r;
    r.x = fmaxf(fmaf(y.x, sc, sh), 0.f);
    r.y = fmaxf(fmaf(y.y, sc, sh), 0.f);
    r.z = fmaxf(fmaf(y.z, sc, sh), 0.f);
    r.w = fmaxf(fmaf(y.w, sc, sh), 0.f);
    if (OUT) {
        float4 h = *(const float4*)&H[f];
        r.x += h.x; r.y += h.y; r.z += h.z; r.w += h.w;
        *(float4*)&H[f] = r;
        *(float4*)&OUT[(((size_t)b * 4 * CC) + (size_t)layer * CC + c) * NN + n] = r;
    } else {
        *(float4*)&H[f] = r;
    }
}

// ---------------- launch --------------------------------------------------------
extern "C" void kernel_launch(void* const* d_in, const int* in_sizes, int n_in,
                              void* d_out, int out_size)
{
    const float* x    = (const float*)d_in[0];
    const int*   mask = (const int*)  d_in[1];
    const float* w1   = (const float*)d_in[2];
    const float* g1   = (const float*)d_in[3];
    const float* b1   = (const float*)d_in[4];
    const float* w2   = (const float*)d_in[5];
    const float* g2   = (const float*)d_in[6];
    const float* b2   = (const float*)d_in[7];
    const float* wqk  = (const float*)d_in[8];
    const float* wv   = (const float*)d_in[9];
    const float* bv   = (const float*)d_in[10];
    const float* wt   = (const float*)d_in[11];
    const float* bt   = (const float*)d_in[12];
    const float* sg   = (const float*)d_in[13];
    const float* sb   = (const float*)d_in[14];
    float* out = (float*)d_out;

    float *p_h, *p_y, *p_q, *p_xv, *p_xr, *p_attn;
    cudaGetSymbolAddress((void**)&p_h,    g_h);
    cudaGetSymbolAddress((void**)&p_y,    g_y);
    cudaGetSymbolAddress((void**)&p_q,    g_q);
    cudaGetSymbolAddress((void**)&p_xv,   g_xv);
    cudaGetSymbolAddress((void**)&p_xr,   g_xr);
    cudaGetSymbolAddress((void**)&p_attn, g_attn);

    const dim3 blk256(256), blk128(128);
    const dim3 grid_g128(NN / 128, BB);          // gemm128
    const dim3 grid_g32(NN / 128, 1, BB);        // wqk (O=32)
    const dim3 grid_e(NN / 128, NN / 128, BB);   // energy
    const dim3 grid_sm(NN, BB);
    const dim3 grid_cp(NN / 256, 8, BB);
    const dim3 grid_cf(NN / 256, BB);
    const dim3 grid_ap(NN / 128, BB);            // apply
    const dim3 grid_bp(CC, 8);
    const dim3 grid_ba((unsigned)(((size_t)BB * CC * NN / 4) / 256));

    // head: two conv+BN+relu
    gemm128<<<grid_g128, blk128>>>(w1, x, nullptr, nullptr, p_y);
    bn_part_kernel<<<grid_bp, blk256>>>(p_y);
    bn_finalize_kernel<<<1, CC>>>(g1, b1);
    bn_apply_kernel<<<grid_ba, blk256>>>(p_y, p_h, nullptr, 0);

    gemm128<<<grid_g128, blk128>>>(w2, p_h, nullptr, nullptr, p_y);
    bn_part_kernel<<<grid_bp, blk256>>>(p_y);
    bn_finalize_kernel<<<1, CC>>>(g2, b2);
    bn_apply_kernel<<<grid_ba, blk256>>>(p_y, p_h, nullptr, 0);

    // 4 offset-attention layers
    for (int i = 0; i < 4; i++) {
        gemm_small<32, 128><<<grid_g32, blk256>>>(wqk + (size_t)i * 32 * CC, p_h, nullptr, nullptr, p_q);
        energy_kernel<<<grid_e, blk128>>>(p_q, p_attn);
        softmax_kernel<<<grid_sm, blk256>>>(p_attn, mask);
        colpart_kernel<<<grid_cp, blk256>>>(p_attn);
        colfin_kernel<<<grid_cf, blk256>>>();
        gemm128<<<grid_g128, blk128>>>(wv + (size_t)i * CC * CC, p_h, nullptr, bv + (size_t)i * CC, p_xv);
        apply_kernel<<<grid_ap, blk128>>>(p_xv, p_attn, p_xr);
        gemm128<<<grid_g128, blk128>>>(wt + (size_t)i * CC * CC, p_h, p_xr, bt + (size_t)i * CC, p_y);
        bn_part_kernel<<<grid_bp, blk256>>>(p_y);
        bn_finalize_kernel<<<1, CC>>>(sg + (size_t)i * CC, sb + (size_t)i * CC);
        bn_apply_kernel<<<grid_ba, blk256>>>(p_y, p_h, out, i);
    }
}

// round 3
// speedup vs baseline: 1.4443x; 1.3509x over previous
#include <cuda_runtime.h>
#include <cstdint>
#include <cstddef>

#define NN 4096
#define CC 128
#define BB 4
#define NEGV (-9e15f)
#define KSPLIT 4

typedef unsigned long long ull;

// ---------------- scratch (device globals: no allocation allowed) -----------
__device__ float g_h[(size_t)BB * CC * NN];                  // 8 MB
__device__ float g_y[(size_t)BB * CC * NN];                  // 8 MB
__device__ float g_q[(size_t)BB * 32 * NN];                  // 2 MB
__device__ float g_xv[(size_t)BB * CC * NN];                 // 8 MB
__device__ float g_xr[(size_t)BB * CC * NN];                 // 8 MB
__device__ float g_xrp[KSPLIT][(size_t)BB * CC * NN];        // 32 MB apply partials
__device__ float g_attn[(size_t)BB * NN * NN];               // 256 MB
__device__ float g_colpart[(size_t)8 * BB * NN];
__device__ float g_colinv[(size_t)BB * NN];
__device__ float g_scale[CC];
__device__ float g_shift[CC];
__device__ float g_bnp1[8][CC];
__device__ float g_bnp2[8][CC];

// ---------------- helpers ----------------------------------------------------
__device__ __forceinline__ float warp_red_sum(float v) {
#pragma unroll
    for (int o = 16; o > 0; o >>= 1) v += __shfl_xor_sync(0xffffffffu, v, o);
    return v;
}
__device__ __forceinline__ float warp_red_max(float v) {
#pragma unroll
    for (int o = 16; o > 0; o >>= 1) v = fmaxf(v, __shfl_xor_sync(0xffffffffu, v, o));
    return v;
}

__device__ __forceinline__ void fma2(ull& acc, ull a, ull b) {
    asm("fma.rn.f32x2 %0, %1, %2, %0;" : "+l"(acc) : "l"(a), "l"(b));
}
__device__ __forceinline__ ull pack2(float v) {
    ull r;
    unsigned u = __float_as_uint(v);
    asm("mov.b64 %0, {%1, %1};" : "=l"(r) : "r"(u));
    return r;
}
__device__ __forceinline__ float2 unpack2(ull v) {
    unsigned lo, hi;
    asm("mov.b64 {%0, %1}, %2;" : "=r"(lo), "=r"(hi) : "l"(v));
    return make_float2(__uint_as_float(lo), __uint_as_float(hi));
}

__device__ __forceinline__ void fma44(float acc[4][4], float4 w, float4 x) {
    acc[0][0] += w.x * x.x; acc[0][1] += w.x * x.y; acc[0][2] += w.x * x.z; acc[0][3] += w.x * x.w;
    acc[1][0] += w.y * x.x; acc[1][1] += w.y * x.y; acc[1][2] += w.y * x.z; acc[1][3] += w.y * x.w;
    acc[2][0] += w.z * x.x; acc[2][1] += w.z * x.y; acc[2][2] += w.z * x.z; acc[2][3] += w.z * x.w;
    acc[3][0] += w.w * x.x; acc[3][1] += w.w * x.y; acc[3][2] += w.w * x.z; acc[3][3] += w.w * x.w;
}

// 8x8 (8 rows x 4 pairs) FMA2 micro-step shared by gemm128/apply
__device__ __forceinline__ void microstep_8x8(
    ull acc[8][4], const float* __restrict__ rowS, const double* __restrict__ pairS,
    int tc, int tp)
{
    float4 xa = *(const float4*)&rowS[tc * 8];
    float4 xb = *(const float4*)&rowS[tc * 8 + 4];
    ull xc[8];
    xc[0] = pack2(xa.x); xc[1] = pack2(xa.y); xc[2] = pack2(xa.z); xc[3] = pack2(xa.w);
    xc[4] = pack2(xb.x); xc[5] = pack2(xb.y); xc[6] = pack2(xb.z); xc[7] = pack2(xb.w);
    ull af[4];
#pragma unroll
    for (int j = 0; j < 4; j++) af[j] = *(const ull*)&pairS[tp + 16 * j];
#pragma unroll
    for (int i = 0; i < 8; i++)
#pragma unroll
        for (int j = 0; j < 4; j++) fma2(acc[i][j], xc[i], af[j]);
}

// ---------------- gemm_small (wqk, O=32) --------------------------------------
template <int BO, int BN>
__global__ __launch_bounds__(256) void gemm_small(
    const float* __restrict__ W, const float* __restrict__ X1,
    const float* __restrict__ X2, const float* __restrict__ bias,
    float* __restrict__ Y)
{
    constexpr int TN = BN / 4;
    __shared__ float Ws[CC][BO];
    __shared__ float Xs[64][BN];

    const int b  = blockIdx.z;
    const int n0 = blockIdx.x * BN;
    const int o0 = blockIdx.y * BO;
    const int tid = threadIdx.x;
    const int Otot = BO * gridDim.y;

    for (int idx = tid; idx < BO * CC; idx += 256) {
        int o = idx / CC, c = idx % CC;
        Ws[c][o] = W[(size_t)(o0 + o) * CC + c];
    }

    const float* x1 = X1 + (size_t)b * CC * NN;
    const float* x2 = X2 ? X2 + (size_t)b * CC * NN : nullptr;

    float acc[4][4] = {};
    const int to = tid / TN, tn = tid % TN;

    for (int c0 = 0; c0 < CC; c0 += 64) {
        __syncthreads();
        for (int idx = tid; idx < 64 * BN; idx += 256) {
            int c = idx / BN, n = idx % BN;
            float v = x1[(size_t)(c0 + c) * NN + n0 + n];
            if (x2) v -= x2[(size_t)(c0 + c) * NN + n0 + n];
            Xs[c][n] = v;
        }
        __syncthreads();
#pragma unroll 8
        for (int c = 0; c < 64; c++) {
            float4 w = *(const float4*)&Ws[c0 + c][to * 4];
            float4 x = *(const float4*)&Xs[c][tn * 4];
            fma44(acc, w, x);
        }
    }

#pragma unroll
    for (int i = 0; i < 4; i++) {
        int o = o0 + to * 4 + i;
        float bi = bias ? bias[o] : 0.f;
        float4 r = make_float4(acc[i][0] + bi, acc[i][1] + bi, acc[i][2] + bi, acc[i][3] + bi);
        *(float4*)&Y[((size_t)b * Otot + o) * NN + n0 + tn * 4] = r;
    }
}

// ---------------- gemm128: Y[b,o,n] = sum_c W[o,c]*(X1-X2)[b,c,n] + bias ------
// 256 threads, tile 128o x 128n, per-thread 8o x 8n via fp32x2.
__global__ __launch_bounds__(256, 2) void gemm128(
    const float* __restrict__ W, const float* __restrict__ X1,
    const float* __restrict__ X2, const float* __restrict__ bias,
    float* __restrict__ Y)
{
    __shared__ float  Ws[32][132];   // [c_local][o]
    __shared__ double Xd[32][66];    // [c_local][n-pairs]

    const int b  = blockIdx.y;
    const int n0 = blockIdx.x * 128;
    const int tid = threadIdx.x;
    const int tp = tid & 15;         // pair group (0..15)
    const int tc = tid >> 4;         // o group (0..15)

    const float* x1 = X1 + (size_t)b * CC * NN;
    const float* x2 = X2 ? X2 + (size_t)b * CC * NN : nullptr;

    ull acc[8][4];
#pragma unroll
    for (int i = 0; i < 8; i++)
#pragma unroll
        for (int j = 0; j < 4; j++) acc[i][j] = 0ull;

    for (int c0 = 0; c0 < CC; c0 += 32) {
        // Ws fill: o = tid&127, half h = tid>>7 covers 16 c's
        {
            int o = tid & 127, h = tid >> 7;
            const float* wsrc = W + (size_t)o * CC + c0 + h * 16;
            float4 wv[4];
#pragma unroll
            for (int r = 0; r < 4; r++) wv[r] = *(const float4*)&wsrc[r * 4];
#pragma unroll
            for (int r = 0; r < 4; r++) {
                int cbase = h * 16 + r * 4;
                Ws[cbase + 0][o] = wv[r].x;
                Ws[cbase + 1][o] = wv[r].y;
                Ws[cbase + 2][o] = wv[r].z;
                Ws[cbase + 3][o] = wv[r].w;
            }
        }
        // Xd fill: 32 rows x 32 float4 = 1024, 4 per thread
#pragma unroll
        for (int t = 0; t < 4; t++) {
            int idx = tid + t * 256;
            int c = idx >> 5, q = idx & 31;
            float4 v = *(const float4*)&x1[(size_t)(c0 + c) * NN + n0 + q * 4];
            if (x2) {
                float4 w = *(const float4*)&x2[(size_t)(c0 + c) * NN + n0 + q * 4];
                v.x -= w.x; v.y -= w.y; v.z -= w.z; v.w -= w.w;
            }
            *(double2*)&Xd[c][q * 2] = *(const double2*)&v;
        }
        __syncthreads();
#pragma unroll
        for (int k = 0; k < 32; k++)
            microstep_8x8(acc, &Ws[k][0], &Xd[k][0], tc, tp);
        __syncthreads();
    }

#pragma unroll
    for (int i = 0; i < 8; i++) {
        int o = tc * 8 + i;
        float bi = bias ? bias[o] : 0.f;
#pragma unroll
        for (int j = 0; j < 4; j++) {
            float2 r = unpack2(acc[i][j]);
            r.x += bi; r.y += bi;
            *(float2*)&Y[((size_t)b * CC + o) * NN + n0 + 2 * (tp + 16 * j)] = r;
        }
    }
}

// ---------------- energy: E[b,n,m] = sum_{o<32} Q[b,o,n]*Q[b,o,m] -------------
__global__ __launch_bounds__(128, 2) void energy_kernel(
    const float* __restrict__ Q, float* __restrict__ E)
{
    __shared__ float  Ns[32][132];
    __shared__ double Md[32][66];

    const int b  = blockIdx.z;
    const int n0 = blockIdx.y * 128;
    const int m0 = blockIdx.x * 128;
    const int tid = threadIdx.x;
    const int tm = tid & 7, tc = tid >> 3;
    const float* q = Q + (size_t)b * 32 * NN;

#pragma unroll
    for (int t = 0; t < 8; t++) {
        int idx = tid + t * 128;
        int o = idx >> 5, qd = idx & 31;
        float4 vn = *(const float4*)&q[(size_t)o * NN + n0 + qd * 4];
        *(float4*)&Ns[o][qd * 4] = vn;
        float4 vm = *(const float4*)&q[(size_t)o * NN + m0 + qd * 4];
        *(double2*)&Md[o][qd * 2] = *(const double2*)&vm;
    }
    __syncthreads();

    ull acc[8][8];
#pragma unroll
    for (int i = 0; i < 8; i++)
#pragma unroll
        for (int j = 0; j < 8; j++) acc[i][j] = 0ull;

#pragma unroll
    for (int k = 0; k < 32; k++) {
        float4 xa = *(const float4*)&Ns[k][tc * 8];
        float4 xb = *(const float4*)&Ns[k][tc * 8 + 4];
        ull xc[8];
        xc[0] = pack2(xa.x); xc[1] = pack2(xa.y); xc[2] = pack2(xa.z); xc[3] = pack2(xa.w);
        xc[4] = pack2(xb.x); xc[5] = pack2(xb.y); xc[6] = pack2(xb.z); xc[7] = pack2(xb.w);
        ull af[8];
#pragma unroll
        for (int j = 0; j < 8; j++) af[j] = *(const ull*)&Md[k][tm + 8 * j];
#pragma unroll
        for (int i = 0; i < 8; i++)
#pragma unroll
            for (int j = 0; j < 8; j++) fma2(acc[i][j], xc[i], af[j]);
    }

#pragma unroll
    for (int i = 0; i < 8; i++) {
        size_t row = (size_t)b * NN + n0 + tc * 8 + i;
#pragma unroll
        for (int j = 0; j < 8; j++) {
            float2 r = unpack2(acc[i][j]);
            *(float2*)&E[row * NN + m0 + 2 * tm + 16 * j] = r;
        }
    }
}

// ---------------- masked row softmax, in place --------------------------------
__global__ __launch_bounds__(256) void softmax_kernel(
    float* __restrict__ E, const int* __restrict__ mask)
{
    const int b = blockIdx.y, n = blockIdx.x;
    float* row = E + ((size_t)b * NN + n) * NN;
    const int* mrow = mask + (size_t)b * NN;
    const int tid = threadIdx.x;
    const int rm = mrow[n];

    float vals[16];
    float vmax = -3.4e38f;
#pragma unroll
    for (int k = 0; k < 4; k++) {
        int j = k * 1024 + tid * 4;
        float4 e = *(const float4*)&row[j];
        int4 mm = *(const int4*)&mrow[j];
        vals[k * 4 + 0] = (rm && mm.x) ? e.x : NEGV;
        vals[k * 4 + 1] = (rm && mm.y) ? e.y : NEGV;
        vals[k * 4 + 2] = (rm && mm.z) ? e.z : NEGV;
        vals[k * 4 + 3] = (rm && mm.w) ? e.w : NEGV;
        vmax = fmaxf(vmax, fmaxf(fmaxf(vals[k*4+0], vals[k*4+1]), fmaxf(vals[k*4+2], vals[k*4+3])));
    }

    __shared__ float rmx[8], rsm[8];
    float wm = warp_red_max(vmax);
    if ((tid & 31) == 0) rmx[tid >> 5] = wm;
    __syncthreads();
    float m8 = rmx[0];
#pragma unroll
    for (int i = 1; i < 8; i++) m8 = fmaxf(m8, rmx[i]);

    float s = 0.f;
#pragma unroll
    for (int i = 0; i < 16; i++) { vals[i] = __expf(vals[i] - m8); s += vals[i]; }
    float ws = warp_red_sum(s);
    if ((tid & 31) == 0) rsm[tid >> 5] = ws;
    __syncthreads();
    float tot = 0.f;
#pragma unroll
    for (int i = 0; i < 8; i++) tot += rsm[i];
    float inv = 1.f / tot;

#pragma unroll
    for (int k = 0; k < 4; k++) {
        int j = k * 1024 + tid * 4;
        float4 r = make_float4(vals[k*4+0]*inv, vals[k*4+1]*inv, vals[k*4+2]*inv, vals[k*4+3]*inv);
        *(float4*)&row[j] = r;
    }
}

// ---------------- column-sum (split over n) -----------------------------------
__global__ __launch_bounds__(256) void colpart_kernel(const float* __restrict__ A)
{
    const int b = blockIdx.z;
    const int split = blockIdx.y;
    const int m = blockIdx.x * 256 + threadIdx.x;
    const float* a = A + (size_t)b * NN * NN + m;
    const int nbeg = split * 512;
    float s0 = 0.f, s1 = 0.f, s2 = 0.f, s3 = 0.f;
#pragma unroll 2
    for (int n = nbeg; n < nbeg + 512; n += 4) {
        s0 += a[(size_t)(n + 0) * NN];
        s1 += a[(size_t)(n + 1) * NN];
        s2 += a[(size_t)(n + 2) * NN];
        s3 += a[(size_t)(n + 3) * NN];
    }
    g_colpart[((size_t)split * BB + b) * NN + m] = (s0 + s1) + (s2 + s3);
}

__global__ __launch_bounds__(256) void colfin_kernel()
{
    const int b = blockIdx.y;
    const int m = blockIdx.x * 256 + threadIdx.x;
    float s = 0.f;
#pragma unroll
    for (int split = 0; split < 8; split++)
        s += g_colpart[((size_t)split * BB + b) * NN + m];
    g_colinv[(size_t)b * NN + m] = 1.f / (1e-9f + s);
}

// ---------------- attn apply partial: K-split GEMM -----------------------------
// XRP[z][b,c,m] = sum_{n in Kz} XV[b,c,n]*A[b,n,m]
// 256 threads, tile 128c x 128m, per-thread 8c x 8m via fp32x2.
__global__ __launch_bounds__(256, 2) void apply_kernel(
    const float* __restrict__ XV, const float* __restrict__ A)
{
    __shared__ float  Xs[32][132];   // [k][c]
    __shared__ double Ad[32][66];    // [k][m-pairs]

    const int b  = blockIdx.y;
    const int m0 = blockIdx.x * 128;
    const int kz = blockIdx.z;
    const int tid = threadIdx.x;
    const int tp = tid & 15, tc = tid >> 4;
    const float* xv = XV + (size_t)b * CC * NN;
    const float* a  = A + (size_t)b * NN * NN;
    float* xrp = &g_xrp[kz][0];

    ull acc[8][4];
#pragma unroll
    for (int i = 0; i < 8; i++)
#pragma unroll
        for (int j = 0; j < 4; j++) acc[i][j] = 0ull;

    const int kbeg = kz * (NN / KSPLIT);
    const int kend = kbeg + (NN / KSPLIT);

    for (int k0 = kbeg; k0 < kend; k0 += 32) {
        // Xs fill: c = tid>>1, half h = tid&1 covers 16 k's
        {
            int c = tid >> 1, h = tid & 1;
            const float* src = xv + (size_t)c * NN + k0 + h * 16;
            float4 v[4];
#pragma unroll
            for (int r = 0; r < 4; r++) v[r] = *(const float4*)&src[r * 4];
#pragma unroll
            for (int r = 0; r < 4; r++) {
                int kbase = h * 16 + r * 4;
                Xs[kbase + 0][c] = v[r].x;
                Xs[kbase + 1][c] = v[r].y;
                Xs[kbase + 2][c] = v[r].z;
                Xs[kbase + 3][c] = v[r].w;
            }
        }
        // Ad fill
#pragma unroll
        for (int t = 0; t < 4; t++) {
            int idx = tid + t * 256;
            int k = idx >> 5, q = idx & 31;
            float4 v = *(const float4*)&a[(size_t)(k0 + k) * NN + m0 + q * 4];
            *(double2*)&Ad[k][q * 2] = *(const double2*)&v;
        }
        __syncthreads();
#pragma unroll
        for (int k = 0; k < 32; k++)
            microstep_8x8(acc, &Xs[k][0], &Ad[k][0], tc, tp);
        __syncthreads();
    }

#pragma unroll
    for (int i = 0; i < 8; i++) {
        int c = tc * 8 + i;
#pragma unroll
        for (int j = 0; j < 4; j++) {
            float2 r = unpack2(acc[i][j]);
            *(float2*)&xrp[((size_t)b * CC + c) * NN + m0 + 2 * (tp + 16 * j)] = r;
        }
    }
}

// ---------------- reduce partials + colinv -------------------------------------
__global__ __launch_bounds__(256) void xr_reduce_kernel(float* __restrict__ XR)
{
    size_t f = ((size_t)blockIdx.x * 256 + threadIdx.x) * 4;
    int n = (int)(f % NN);
    int b = (int)(f / ((size_t)NN * CC));
    float4 s = *(const float4*)&g_xrp[0][f];
#pragma unroll
    for (int z = 1; z < KSPLIT; z++) {
        float4 p = *(const float4*)&g_xrp[z][f];
        s.x += p.x; s.y += p.y; s.z += p.z; s.w += p.w;
    }
    float4 ci = *(const float4*)&g_colinv[(size_t)b * NN + n];
    s.x *= ci.x; s.y *= ci.y; s.z *= ci.z; s.w *= ci.w;
    *(float4*)&XR[f] = s;
}

// ---------------- BN stats: 8-way partials + finalize ---------------------------
__global__ __launch_bounds__(256) void bn_part_kernel(const float* __restrict__ Y)
{
    const int c = blockIdx.x;
    const int s = blockIdx.y;
    const int b = s >> 1;
    const int n0 = (s & 1) * 2048;
    const float* p = Y + ((size_t)b * CC + c) * NN + n0;
    const int tid = threadIdx.x;
    float sum = 0.f, sq = 0.f;
#pragma unroll
    for (int i = 0; i < 8; i++) {
        float v = p[tid + i * 256];
        sum += v; sq += v * v;
    }
    sum = warp_red_sum(sum); sq = warp_red_sum(sq);
    __shared__ float r1[8], r2[8];
    if ((tid & 31) == 0) { r1[tid >> 5] = sum; r2[tid >> 5] = sq; }
    __syncthreads();
    if (tid == 0) {
        float ts = 0.f, t2 = 0.f;
#pragma unroll
        for (int i = 0; i < 8; i++) { ts += r1[i]; t2 += r2[i]; }
        g_bnp1[s][c] = ts;
        g_bnp2[s][c] = t2;
    }
}

__global__ void bn_finalize_kernel(const float* __restrict__ gam, const float* __restrict__ bet)
{
    const int c = threadIdx.x;
    float ts = 0.f, t2 = 0.f;
#pragma unroll
    for (int s = 0; s < 8; s++) { ts += g_bnp1[s][c]; t2 += g_bnp2[s][c]; }
    const float invN = 1.f / (float)(BB * NN);
    float mean = ts * invN;
    float var  = t2 * invN - mean * mean;
    float sc = gam[c] * rsqrtf(var + 1e-5f);
    g_scale[c] = sc;
    g_shift[c] = bet[c] - mean * sc;
}

// ---------------- BN apply (+relu) [+residual into h and output slab] -----------
__global__ __launch_bounds__(256) void bn_apply_kernel(
    const float* __restrict__ Y, float* __restrict__ H,
    float* __restrict__ OUT, int layer)
{
    size_t f = ((size_t)blockIdx.x * 256 + threadIdx.x) * 4;
    int n = (int)(f % NN);
    int c = (int)((f / NN) % CC);
    int b = (int)(f / ((size_t)NN * CC));
    float sc = g_scale[c], sh = g_shift[c];
    float4 y = *(const float4*)&Y[f];
    float4 r;
    r.x = fmaxf(fmaf(y.x, sc, sh), 0.f);
    r.y = fmaxf(fmaf(y.y, sc, sh), 0.f);
    r.z = fmaxf(fmaf(y.z, sc, sh), 0.f);
    r.w = fmaxf(fmaf(y.w, sc, sh), 0.f);
    if (OUT) {
        float4 h = *(const float4*)&H[f];
        r.x += h.x; r.y += h.y; r.z += h.z; r.w += h.w;
        *(float4*)&H[f] = r;
        *(float4*)&OUT[(((size_t)b * 4 * CC) + (size_t)layer * CC + c) * NN + n] = r;
    } else {
        *(float4*)&H[f] = r;
    }
}

// ---------------- launch ---------------------------------------------------------
extern "C" void kernel_launch(void* const* d_in, const int* in_sizes, int n_in,
                              void* d_out, int out_size)
{
    const float* x    = (const float*)d_in[0];
    const int*   mask = (const int*)  d_in[1];
    const float* w1   = (const float*)d_in[2];
    const float* g1   = (const float*)d_in[3];
    const float* b1   = (const float*)d_in[4];
    const float* w2   = (const float*)d_in[5];
    const float* g2   = (const float*)d_in[6];
    const float* b2   = (const float*)d_in[7];
    const float* wqk  = (const float*)d_in[8];
    const float* wv   = (const float*)d_in[9];
    const float* bv   = (const float*)d_in[10];
    const float* wt   = (const float*)d_in[11];
    const float* bt   = (const float*)d_in[12];
    const float* sg   = (const float*)d_in[13];
    const float* sb   = (const float*)d_in[14];
    float* out = (float*)d_out;

    float *p_h, *p_y, *p_q, *p_xv, *p_xr, *p_attn;
    cudaGetSymbolAddress((void**)&p_h,    g_h);
    cudaGetSymbolAddress((void**)&p_y,    g_y);
    cudaGetSymbolAddress((void**)&p_q,    g_q);
    cudaGetSymbolAddress((void**)&p_xv,   g_xv);
    cudaGetSymbolAddress((void**)&p_xr,   g_xr);
    cudaGetSymbolAddress((void**)&p_attn, g_attn);

    const dim3 blk256(256), blk128(128);
    const dim3 grid_g128(NN / 128, BB);
    const dim3 grid_g32(NN / 128, 1, BB);
    const dim3 grid_e(NN / 128, NN / 128, BB);
    const dim3 grid_sm(NN, BB);
    const dim3 grid_cp(NN / 256, 8, BB);
    const dim3 grid_cf(NN / 256, BB);
    const dim3 grid_ap(NN / 128, BB, KSPLIT);
    const dim3 grid_bp(CC, 8);
    const dim3 grid_ba((unsigned)(((size_t)BB * CC * NN / 4) / 256));

    // head: two conv+BN+relu
    gemm128<<<grid_g128, blk256>>>(w1, x, nullptr, nullptr, p_y);
    bn_part_kernel<<<grid_bp, blk256>>>(p_y);
    bn_finalize_kernel<<<1, CC>>>(g1, b1);
    bn_apply_kernel<<<grid_ba, blk256>>>(p_y, p_h, nullptr, 0);

    gemm128<<<grid_g128, blk256>>>(w2, p_h, nullptr, nullptr, p_y);
    bn_part_kernel<<<grid_bp, blk256>>>(p_y);
    bn_finalize_kernel<<<1, CC>>>(g2, b2);
    bn_apply_kernel<<<grid_ba, blk256>>>(p_y, p_h, nullptr, 0);

    // 4 offset-attention layers
    for (int i = 0; i < 4; i++) {
        gemm_small<32, 128><<<grid_g32, blk256>>>(wqk + (size_t)i * 32 * CC, p_h, nullptr, nullptr, p_q);
        energy_kernel<<<grid_e, blk128>>>(p_q, p_attn);
        softmax_kernel<<<grid_sm, blk256>>>(p_attn, mask);
        colpart_kernel<<<grid_cp, blk256>>>(p_attn);
        colfin_kernel<<<grid_cf, blk256>>>();
        gemm128<<<grid_g128, blk256>>>(wv + (size_t)i * CC * CC, p_h, nullptr, bv + (size_t)i * CC, p_xv);
        apply_kernel<<<grid_ap, blk256>>>(p_xv, p_attn);
        xr_reduce_kernel<<<grid_ba, blk256>>>(p_xr);
        gemm128<<<grid_g128, blk256>>>(wt + (size_t)i * CC * CC, p_h, p_xr, bt + (size_t)i * CC, p_y);
        bn_part_kernel<<<grid_bp, blk256>>>(p_y);
        bn_finalize_kernel<<<1, CC>>>(sg + (size_t)i * CC, sb + (size_t)i * CC);
        bn_apply_kernel<<<grid_ba, blk256>>>(p_y, p_h, out, i);
    }
}

// round 4
// speedup vs baseline: 2.6989x; 1.8686x over previous
#include <cuda_runtime.h>
#include <cuda_fp16.h>
#include <cstdint>
#include <cstddef>

#define NN 4096
#define CC 128
#define BB 4
#define NEGV (-9e15f)

typedef unsigned long long ull;

// ---------------- scratch (device globals: no allocation allowed) -----------
__device__ float  g_h[(size_t)BB * CC * NN];                 // 8 MB
__device__ float  g_y[(size_t)BB * CC * NN];                 // 8 MB
__device__ float  g_q[(size_t)BB * 32 * NN];                 // 2 MB
__device__ __half g_xvh[(size_t)BB * CC * NN];               // 4 MB  value proj fp16
__device__ float  g_xr[(size_t)BB * CC * NN];                // 8 MB
__device__ float  g_attn[(size_t)BB * NN * NN];              // 256 MB energy fp32
__device__ __half g_attn_h[(size_t)BB * NN * NN];            // 128 MB attn fp16
__device__ float  g_colpart[(size_t)8 * BB * NN];
__device__ float  g_colinv[(size_t)BB * NN];
__device__ float  g_scale[CC];
__device__ float  g_shift[CC];
__device__ float  g_bnp1[8][CC];
__device__ float  g_bnp2[8][CC];

// ---------------- helpers ----------------------------------------------------
__device__ __forceinline__ float warp_red_sum(float v) {
#pragma unroll
    for (int o = 16; o > 0; o >>= 1) v += __shfl_xor_sync(0xffffffffu, v, o);
    return v;
}
__device__ __forceinline__ float warp_red_max(float v) {
#pragma unroll
    for (int o = 16; o > 0; o >>= 1) v = fmaxf(v, __shfl_xor_sync(0xffffffffu, v, o));
    return v;
}

__device__ __forceinline__ void fma2(ull& acc, ull a, ull b) {
    asm("fma.rn.f32x2 %0, %1, %2, %0;" : "+l"(acc) : "l"(a), "l"(b));
}
__device__ __forceinline__ ull pack2(float v) {
    ull r;
    unsigned u = __float_as_uint(v);
    asm("mov.b64 %0, {%1, %1};" : "=l"(r) : "r"(u));
    return r;
}
__device__ __forceinline__ float2 unpack2(ull v) {
    unsigned lo, hi;
    asm("mov.b64 {%0, %1}, %2;" : "=r"(lo), "=r"(hi) : "l"(v));
    return make_float2(__uint_as_float(lo), __uint_as_float(hi));
}

__device__ __forceinline__ void fma44(float acc[4][4], float4 w, float4 x) {
    acc[0][0] += w.x * x.x; acc[0][1] += w.x * x.y; acc[0][2] += w.x * x.z; acc[0][3] += w.x * x.w;
    acc[1][0] += w.y * x.x; acc[1][1] += w.y * x.y; acc[1][2] += w.y * x.z; acc[1][3] += w.y * x.w;
    acc[2][0] += w.z * x.x; acc[2][1] += w.z * x.y; acc[2][2] += w.z * x.z; acc[2][3] += w.z * x.w;
    acc[3][0] += w.w * x.x; acc[3][1] += w.w * x.y; acc[3][2] += w.w * x.z; acc[3][3] += w.w * x.w;
}

// 8x8 (8 rows x 4 pairs) FMA2 micro-step
__device__ __forceinline__ void microstep_8x8(
    ull acc[8][4], const float* __restrict__ rowS, const double* __restrict__ pairS,
    int tc, int tp)
{
    float4 xa = *(const float4*)&rowS[tc * 8];
    float4 xb = *(const float4*)&rowS[tc * 8 + 4];
    ull xc[8];
    xc[0] = pack2(xa.x); xc[1] = pack2(xa.y); xc[2] = pack2(xa.z); xc[3] = pack2(xa.w);
    xc[4] = pack2(xb.x); xc[5] = pack2(xb.y); xc[6] = pack2(xb.z); xc[7] = pack2(xb.w);
    ull af[4];
#pragma unroll
    for (int j = 0; j < 4; j++) af[j] = *(const ull*)&pairS[tp + 16 * j];
#pragma unroll
    for (int i = 0; i < 8; i++)
#pragma unroll
        for (int j = 0; j < 4; j++) fma2(acc[i][j], xc[i], af[j]);
}

// ---------------- HMMA helpers -------------------------------------------------
__device__ __forceinline__ void ldsm_x4(unsigned& r0, unsigned& r1, unsigned& r2, unsigned& r3,
                                        const void* p) {
    unsigned addr = (unsigned)__cvta_generic_to_shared(p);
    asm volatile("ldmatrix.sync.aligned.m8n8.x4.shared.b16 {%0,%1,%2,%3}, [%4];"
        : "=r"(r0), "=r"(r1), "=r"(r2), "=r"(r3) : "r"(addr));
}
__device__ __forceinline__ void ldsm_x4_t(unsigned& r0, unsigned& r1, unsigned& r2, unsigned& r3,
                                          const void* p) {
    unsigned addr = (unsigned)__cvta_generic_to_shared(p);
    asm volatile("ldmatrix.sync.aligned.m8n8.x4.trans.shared.b16 {%0,%1,%2,%3}, [%4];"
        : "=r"(r0), "=r"(r1), "=r"(r2), "=r"(r3) : "r"(addr));
}
__device__ __forceinline__ void mma16816(float d[4], const unsigned a[4], const unsigned b[2]) {
    asm volatile("mma.sync.aligned.m16n8k16.row.col.f32.f16.f16.f32 "
        "{%0,%1,%2,%3}, {%4,%5,%6,%7}, {%8,%9}, {%0,%1,%2,%3};"
        : "+f"(d[0]), "+f"(d[1]), "+f"(d[2]), "+f"(d[3])
        : "r"(a[0]), "r"(a[1]), "r"(a[2]), "r"(a[3]), "r"(b[0]), "r"(b[1]));
}

// ---------------- gemm_small (wqk, O=32) --------------------------------------
template <int BO, int BN>
__global__ __launch_bounds__(256) void gemm_small(
    const float* __restrict__ W, const float* __restrict__ X1,
    const float* __restrict__ X2, const float* __restrict__ bias,
    float* __restrict__ Y)
{
    constexpr int TN = BN / 4;
    __shared__ float Ws[CC][BO];
    __shared__ float Xs[64][BN];

    const int b  = blockIdx.z;
    const int n0 = blockIdx.x * BN;
    const int o0 = blockIdx.y * BO;
    const int tid = threadIdx.x;
    const int Otot = BO * gridDim.y;

    for (int idx = tid; idx < BO * CC; idx += 256) {
        int o = idx / CC, c = idx % CC;
        Ws[c][o] = W[(size_t)(o0 + o) * CC + c];
    }

    const float* x1 = X1 + (size_t)b * CC * NN;
    const float* x2 = X2 ? X2 + (size_t)b * CC * NN : nullptr;

    float acc[4][4] = {};
    const int to = tid / TN, tn = tid % TN;

    for (int c0 = 0; c0 < CC; c0 += 64) {
        __syncthreads();
        for (int idx = tid; idx < 64 * BN; idx += 256) {
            int c = idx / BN, n = idx % BN;
            float v = x1[(size_t)(c0 + c) * NN + n0 + n];
            if (x2) v -= x2[(size_t)(c0 + c) * NN + n0 + n];
            Xs[c][n] = v;
        }
        __syncthreads();
#pragma unroll 8
        for (int c = 0; c < 64; c++) {
            float4 w = *(const float4*)&Ws[c0 + c][to * 4];
            float4 x = *(const float4*)&Xs[c][tn * 4];
            fma44(acc, w, x);
        }
    }

#pragma unroll
    for (int i = 0; i < 4; i++) {
        int o = o0 + to * 4 + i;
        float bi = bias ? bias[o] : 0.f;
        float4 r = make_float4(acc[i][0] + bi, acc[i][1] + bi, acc[i][2] + bi, acc[i][3] + bi);
        *(float4*)&Y[((size_t)b * Otot + o) * NN + n0 + tn * 4] = r;
    }
}

// ---------------- gemm128: Y[b,o,n] = sum_c W[o,c]*(X1-X2)[b,c,n] + bias ------
// 256 threads, tile 128o x 128n, per-thread 8o x 8n via fp32x2.
// If Yh != nullptr, writes fp16 to Yh instead of fp32 to Y.
__global__ __launch_bounds__(256, 2) void gemm128(
    const float* __restrict__ W, const float* __restrict__ X1,
    const float* __restrict__ X2, const float* __restrict__ bias,
    float* __restrict__ Y, __half* __restrict__ Yh)
{
    __shared__ float  Ws[32][132];
    __shared__ double Xd[32][66];

    const int b  = blockIdx.y;
    const int n0 = blockIdx.x * 128;
    const int tid = threadIdx.x;
    const int tp = tid & 15;
    const int tc = tid >> 4;

    const float* x1 = X1 + (size_t)b * CC * NN;
    const float* x2 = X2 ? X2 + (size_t)b * CC * NN : nullptr;

    ull acc[8][4];
#pragma unroll
    for (int i = 0; i < 8; i++)
#pragma unroll
        for (int j = 0; j < 4; j++) acc[i][j] = 0ull;

    for (int c0 = 0; c0 < CC; c0 += 32) {
        {
            int o = tid & 127, h = tid >> 7;
            const float* wsrc = W + (size_t)o * CC + c0 + h * 16;
            float4 wv[4];
#pragma unroll
            for (int r = 0; r < 4; r++) wv[r] = *(const float4*)&wsrc[r * 4];
#pragma unroll
            for (int r = 0; r < 4; r++) {
                int cbase = h * 16 + r * 4;
                Ws[cbase + 0][o] = wv[r].x;
                Ws[cbase + 1][o] = wv[r].y;
                Ws[cbase + 2][o] = wv[r].z;
                Ws[cbase + 3][o] = wv[r].w;
            }
        }
#pragma unroll
        for (int t = 0; t < 4; t++) {
            int idx = tid + t * 256;
            int c = idx >> 5, q = idx & 31;
            float4 v = *(const float4*)&x1[(size_t)(c0 + c) * NN + n0 + q * 4];
            if (x2) {
                float4 w = *(const float4*)&x2[(size_t)(c0 + c) * NN + n0 + q * 4];
                v.x -= w.x; v.y -= w.y; v.z -= w.z; v.w -= w.w;
            }
            *(double2*)&Xd[c][q * 2] = *(const double2*)&v;
        }
        __syncthreads();
#pragma unroll
        for (int k = 0; k < 32; k++)
            microstep_8x8(acc, &Ws[k][0], &Xd[k][0], tc, tp);
        __syncthreads();
    }

#pragma unroll
    for (int i = 0; i < 8; i++) {
        int o = tc * 8 + i;
        float bi = bias ? bias[o] : 0.f;
#pragma unroll
        for (int j = 0; j < 4; j++) {
            float2 r = unpack2(acc[i][j]);
            r.x += bi; r.y += bi;
            size_t off = ((size_t)b * CC + o) * NN + n0 + 2 * (tp + 16 * j);
            if (Yh) {
                *(__half2*)&Yh[off] = __floats2half2_rn(r.x, r.y);
            } else {
                *(float2*)&Y[off] = r;
            }
        }
    }
}

// ---------------- energy: E[b,n,m] = sum_{o<32} Q[b,o,n]*Q[b,o,m] -------------
__global__ __launch_bounds__(128, 2) void energy_kernel(
    const float* __restrict__ Q, float* __restrict__ E)
{
    __shared__ float  Ns[32][132];
    __shared__ double Md[32][66];

    const int b  = blockIdx.z;
    const int n0 = blockIdx.y * 128;
    const int m0 = blockIdx.x * 128;
    const int tid = threadIdx.x;
    const int tm = tid & 7, tc = tid >> 3;
    const float* q = Q + (size_t)b * 32 * NN;

#pragma unroll
    for (int t = 0; t < 8; t++) {
        int idx = tid + t * 128;
        int o = idx >> 5, qd = idx & 31;
        float4 vn = *(const float4*)&q[(size_t)o * NN + n0 + qd * 4];
        *(float4*)&Ns[o][qd * 4] = vn;
        float4 vm = *(const float4*)&q[(size_t)o * NN + m0 + qd * 4];
        *(double2*)&Md[o][qd * 2] = *(const double2*)&vm;
    }
    __syncthreads();

    ull acc[8][8];
#pragma unroll
    for (int i = 0; i < 8; i++)
#pragma unroll
        for (int j = 0; j < 8; j++) acc[i][j] = 0ull;

#pragma unroll
    for (int k = 0; k < 32; k++) {
        float4 xa = *(const float4*)&Ns[k][tc * 8];
        float4 xb = *(const float4*)&Ns[k][tc * 8 + 4];
        ull xc[8];
        xc[0] = pack2(xa.x); xc[1] = pack2(xa.y); xc[2] = pack2(xa.z); xc[3] = pack2(xa.w);
        xc[4] = pack2(xb.x); xc[5] = pack2(xb.y); xc[6] = pack2(xb.z); xc[7] = pack2(xb.w);
        ull af[8];
#pragma unroll
        for (int j = 0; j < 8; j++) af[j] = *(const ull*)&Md[k][tm + 8 * j];
#pragma unroll
        for (int i = 0; i < 8; i++)
#pragma unroll
            for (int j = 0; j < 8; j++) fma2(acc[i][j], xc[i], af[j]);
    }

#pragma unroll
    for (int i = 0; i < 8; i++) {
        size_t row = (size_t)b * NN + n0 + tc * 8 + i;
#pragma unroll
        for (int j = 0; j < 8; j++) {
            float2 r = unpack2(acc[i][j]);
            *(float2*)&E[row * NN + m0 + 2 * tm + 16 * j] = r;
        }
    }
}

// ---------------- masked row softmax: fp32 energy in -> fp16 attn out ----------
__global__ __launch_bounds__(256) void softmax_kernel(
    const float* __restrict__ E, __half* __restrict__ AH, const int* __restrict__ mask)
{
    const int b = blockIdx.y, n = blockIdx.x;
    const float* row = E + ((size_t)b * NN + n) * NN;
    __half* rowh = AH + ((size_t)b * NN + n) * NN;
    const int* mrow = mask + (size_t)b * NN;
    const int tid = threadIdx.x;
    const int rm = mrow[n];

    float vals[16];
    float vmax = -3.4e38f;
#pragma unroll
    for (int k = 0; k < 4; k++) {
        int j = k * 1024 + tid * 4;
        float4 e = *(const float4*)&row[j];
        int4 mm = *(const int4*)&mrow[j];
        vals[k * 4 + 0] = (rm && mm.x) ? e.x : NEGV;
        vals[k * 4 + 1] = (rm && mm.y) ? e.y : NEGV;
        vals[k * 4 + 2] = (rm && mm.z) ? e.z : NEGV;
        vals[k * 4 + 3] = (rm && mm.w) ? e.w : NEGV;
        vmax = fmaxf(vmax, fmaxf(fmaxf(vals[k*4+0], vals[k*4+1]), fmaxf(vals[k*4+2], vals[k*4+3])));
    }

    __shared__ float rmx[8], rsm[8];
    float wm = warp_red_max(vmax);
    if ((tid & 31) == 0) rmx[tid >> 5] = wm;
    __syncthreads();
    float m8 = rmx[0];
#pragma unroll
    for (int i = 1; i < 8; i++) m8 = fmaxf(m8, rmx[i]);

    float s = 0.f;
#pragma unroll
    for (int i = 0; i < 16; i++) { vals[i] = __expf(vals[i] - m8); s += vals[i]; }
    float ws = warp_red_sum(s);
    if ((tid & 31) == 0) rsm[tid >> 5] = ws;
    __syncthreads();
    float tot = 0.f;
#pragma unroll
    for (int i = 0; i < 8; i++) tot += rsm[i];
    float inv = 1.f / tot;

#pragma unroll
    for (int k = 0; k < 4; k++) {
        int j = k * 1024 + tid * 4;
        __half2 h0 = __floats2half2_rn(vals[k*4+0]*inv, vals[k*4+1]*inv);
        __half2 h1 = __floats2half2_rn(vals[k*4+2]*inv, vals[k*4+3]*inv);
        uint2 pk;
        pk.x = *(unsigned*)&h0;
        pk.y = *(unsigned*)&h1;
        *(uint2*)&rowh[j] = pk;
    }
}

// ---------------- column-sum (fp16 attn, split over n) -------------------------
__global__ __launch_bounds__(256) void colpart_kernel(const __half* __restrict__ AH)
{
    const int b = blockIdx.z;
    const int split = blockIdx.y;
    const int m2 = blockIdx.x * 256 + threadIdx.x;      // half2 column index
    const __half2* a = (const __half2*)(AH + (size_t)b * NN * NN) + m2;
    const int nbeg = split * 512;
    float2 s0 = make_float2(0.f, 0.f), s1 = make_float2(0.f, 0.f);
#pragma unroll 4
    for (int n = nbeg; n < nbeg + 512; n += 2) {
        float2 f0 = __half22float2(a[(size_t)(n + 0) * (NN / 2)]);
        float2 f1 = __half22float2(a[(size_t)(n + 1) * (NN / 2)]);
        s0.x += f0.x; s0.y += f0.y;
        s1.x += f1.x; s1.y += f1.y;
    }
    float2 r = make_float2(s0.x + s1.x, s0.y + s1.y);
    *(float2*)&g_colpart[((size_t)split * BB + b) * NN + 2 * m2] = r;
}

__global__ __launch_bounds__(256) void colfin_kernel()
{
    const int b = blockIdx.y;
    const int m = blockIdx.x * 256 + threadIdx.x;
    float s = 0.f;
#pragma unroll
    for (int split = 0; split < 8; split++)
        s += g_colpart[((size_t)split * BB + b) * NN + m];
    g_colinv[(size_t)b * NN + m] = 1.f / (1e-9f + s);
}

// ---------------- attn apply via HMMA: XR[b,c,m] = (sum_n XV*A)*colinv[m] ------
// 256 threads = 8 warps (2c x 4m), block tile 64c x 128m, K chunks of 64.
__global__ __launch_bounds__(256, 2) void apply_hmma(
    const __half* __restrict__ XVH, const __half* __restrict__ AH,
    float* __restrict__ XR)
{
    __shared__ __half XVs[64][72];    // [c][k]
    __shared__ __half As[64][136];    // [k][m]

    const int b  = blockIdx.z;
    const int c0 = blockIdx.y * 64;
    const int m0 = blockIdx.x * 128;
    const int tid = threadIdx.x;
    const int wid = tid >> 5, lane = tid & 31;
    const int wc = wid & 1, wm = wid >> 1;

    const __half* xv = XVH + (size_t)b * CC * NN;
    const __half* at = AH + (size_t)b * NN * NN;

    float acc[2][4][4];
#pragma unroll
    for (int i = 0; i < 2; i++)
#pragma unroll
        for (int j = 0; j < 4; j++)
#pragma unroll
            for (int k = 0; k < 4; k++) acc[i][j][k] = 0.f;

    const int lrow = (lane & 7) + ((lane >> 3) & 1) * 8;
    const int lsel = lane >> 4;
    const int g = lane >> 3;

    for (int k0 = 0; k0 < NN; k0 += 64) {
#pragma unroll
        for (int u = 0; u < 2; u++) {
            int idx = tid + u * 256;
            int r = idx >> 3, s = idx & 7;
            *(uint4*)&XVs[r][s * 8] = *(const uint4*)&xv[(size_t)(c0 + r) * NN + k0 + s * 8];
        }
#pragma unroll
        for (int u = 0; u < 4; u++) {
            int idx = tid + u * 256;
            int r = idx >> 4, s = idx & 15;
            *(uint4*)&As[r][s * 8] = *(const uint4*)&at[(size_t)(k0 + r) * NN + m0 + s * 8];
        }
        __syncthreads();

#pragma unroll
        for (int kk = 0; kk < 4; kk++) {
            unsigned a[2][4];
#pragma unroll
            for (int ci = 0; ci < 2; ci++)
                ldsm_x4(a[ci][0], a[ci][1], a[ci][2], a[ci][3],
                        &XVs[wc * 32 + ci * 16 + lrow][kk * 16 + lsel * 8]);
            unsigned bf[4][2];
#pragma unroll
            for (int h = 0; h < 2; h++) {
                unsigned t0, t1, t2, t3;
                ldsm_x4_t(t0, t1, t2, t3,
                          &As[kk * 16 + (g & 1) * 8 + (lane & 7)][wm * 32 + h * 16 + (g >> 1) * 8]);
                bf[h * 2 + 0][0] = t0; bf[h * 2 + 0][1] = t1;
                bf[h * 2 + 1][0] = t2; bf[h * 2 + 1][1] = t3;
            }
#pragma unroll
            for (int ci = 0; ci < 2; ci++)
#pragma unroll
                for (int nf = 0; nf < 4; nf++)
                    mma16816(acc[ci][nf], a[ci], bf[nf]);
        }
        __syncthreads();
    }

    const float* cinv = g_colinv + (size_t)b * NN + m0;
    const int r0l = lane >> 2, c0l = (lane & 3) * 2;
#pragma unroll
    for (int ci = 0; ci < 2; ci++) {
#pragma unroll
        for (int nf = 0; nf < 4; nf++) {
            int c = c0 + wc * 32 + ci * 16 + r0l;
            int mm = wm * 32 + nf * 8 + c0l;
            float2 cv = *(const float2*)&cinv[mm];
            float2 lo = make_float2(acc[ci][nf][0] * cv.x, acc[ci][nf][1] * cv.y);
            *(float2*)&XR[((size_t)b * CC + c) * NN + m0 + mm] = lo;
            float2 hi = make_float2(acc[ci][nf][2] * cv.x, acc[ci][nf][3] * cv.y);
            *(float2*)&XR[((size_t)b * CC + c + 8) * NN + m0 + mm] = hi;
        }
    }
}

// ---------------- BN stats: 8-way partials + finalize ---------------------------
__global__ __launch_bounds__(256) void bn_part_kernel(const float* __restrict__ Y)
{
    const int c = blockIdx.x;
    const int s = blockIdx.y;
    const int b = s >> 1;
    const int n0 = (s & 1) * 2048;
    const float* p = Y + ((size_t)b * CC + c) * NN + n0;
    const int tid = threadIdx.x;
    float sum = 0.f, sq = 0.f;
#pragma unroll
    for (int i = 0; i < 8; i++) {
        float v = p[tid + i * 256];
        sum += v; sq += v * v;
    }
    sum = warp_red_sum(sum); sq = warp_red_sum(sq);
    __shared__ float r1[8], r2[8];
    if ((tid & 31) == 0) { r1[tid >> 5] = sum; r2[tid >> 5] = sq; }
    __syncthreads();
    if (tid == 0) {
        float ts = 0.f, t2 = 0.f;
#pragma unroll
        for (int i = 0; i < 8; i++) { ts += r1[i]; t2 += r2[i]; }
        g_bnp1[s][c] = ts;
        g_bnp2[s][c] = t2;
    }
}

__global__ void bn_finalize_kernel(const float* __restrict__ gam, const float* __restrict__ bet)
{
    const int c = threadIdx.x;
    float ts = 0.f, t2 = 0.f;
#pragma unroll
    for (int s = 0; s < 8; s++) { ts += g_bnp1[s][c]; t2 += g_bnp2[s][c]; }
    const float invN = 1.f / (float)(BB * NN);
    float mean = ts * invN;
    float var  = t2 * invN - mean * mean;
    float sc = gam[c] * rsqrtf(var + 1e-5f);
    g_scale[c] = sc;
    g_shift[c] = bet[c] - mean * sc;
}

// ---------------- BN apply (+relu) [+residual into h and output slab] -----------
__global__ __launch_bounds__(256) void bn_apply_kernel(
    const float* __restrict__ Y, float* __restrict__ H,
    float* __restrict__ OUT, int layer)
{
    size_t f = ((size_t)blockIdx.x * 256 + threadIdx.x) * 4;
    int n = (int)(f % NN);
    int c = (int)((f / NN) % CC);
    int b = (int)(f / ((size_t)NN * CC));
    float sc = g_scale[c], sh = g_shift[c];
    float4 y = *(const float4*)&Y[f];
    float4 r;
    r.x = fmaxf(fmaf(y.x, sc, sh), 0.f);
    r.y = fmaxf(fmaf(y.y, sc, sh), 0.f);
    r.z = fmaxf(fmaf(y.z, sc, sh), 0.f);
    r.w = fmaxf(fmaf(y.w, sc, sh), 0.f);
    if (OUT) {
        float4 h = *(const float4*)&H[f];
        r.x += h.x; r.y += h.y; r.z += h.z; r.w += h.w;
        *(float4*)&H[f] = r;
        *(float4*)&OUT[(((size_t)b * 4 * CC) + (size_t)layer * CC + c) * NN + n] = r;
    } else {
        *(float4*)&H[f] = r;
    }
}

// ---------------- launch ---------------------------------------------------------
extern "C" void kernel_launch(void* const* d_in, const int* in_sizes, int n_in,
                              void* d_out, int out_size)
{
    const float* x    = (const float*)d_in[0];
    const int*   mask = (const int*)  d_in[1];
    const float* w1   = (const float*)d_in[2];
    const float* g1   = (const float*)d_in[3];
    const float* b1   = (const float*)d_in[4];
    const float* w2   = (const float*)d_in[5];
    const float* g2   = (const float*)d_in[6];
    const float* b2   = (const float*)d_in[7];
    const float* wqk  = (const float*)d_in[8];
    const float* wv   = (const float*)d_in[9];
    const float* bv   = (const float*)d_in[10];
    const float* wt   = (const float*)d_in[11];
    const float* bt   = (const float*)d_in[12];
    const float* sg   = (const float*)d_in[13];
    const float* sb   = (const float*)d_in[14];
    float* out = (float*)d_out;

    float *p_h, *p_y, *p_q, *p_xr, *p_attn;
    __half *p_xvh, *p_attnh;
    cudaGetSymbolAddress((void**)&p_h,     g_h);
    cudaGetSymbolAddress((void**)&p_y,     g_y);
    cudaGetSymbolAddress((void**)&p_q,     g_q);
    cudaGetSymbolAddress((void**)&p_xvh,   g_xvh);
    cudaGetSymbolAddress((void**)&p_xr,    g_xr);
    cudaGetSymbolAddress((void**)&p_attn,  g_attn);
    cudaGetSymbolAddress((void**)&p_attnh, g_attn_h);

    const dim3 blk256(256), blk128(128);
    const dim3 grid_g128(NN / 128, BB);
    const dim3 grid_g32(NN / 128, 1, BB);
    const dim3 grid_e(NN / 128, NN / 128, BB);
    const dim3 grid_sm(NN, BB);
    const dim3 grid_cp(NN / 512, 8, BB);
    const dim3 grid_cf(NN / 256, BB);
    const dim3 grid_ap(NN / 128, CC / 64, BB);
    const dim3 grid_bp(CC, 8);
    const dim3 grid_ba((unsigned)(((size_t)BB * CC * NN / 4) / 256));

    // head: two conv+BN+relu
    gemm128<<<grid_g128, blk256>>>(w1, x, nullptr, nullptr, p_y, nullptr);
    bn_part_kernel<<<grid_bp, blk256>>>(p_y);
    bn_finalize_kernel<<<1, CC>>>(g1, b1);
    bn_apply_kernel<<<grid_ba, blk256>>>(p_y, p_h, nullptr, 0);

    gemm128<<<grid_g128, blk256>>>(w2, p_h, nullptr, nullptr, p_y, nullptr);
    bn_part_kernel<<<grid_bp, blk256>>>(p_y);
    bn_finalize_kernel<<<1, CC>>>(g2, b2);
    bn_apply_kernel<<<grid_ba, blk256>>>(p_y, p_h, nullptr, 0);

    // 4 offset-attention layers
    for (int i = 0; i < 4; i++) {
        gemm_small<32, 128><<<grid_g32, blk256>>>(wqk + (size_t)i * 32 * CC, p_h, nullptr, nullptr, p_q);
        energy_kernel<<<grid_e, blk128>>>(p_q, p_attn);
        softmax_kernel<<<grid_sm, blk256>>>(p_attn, p_attnh, mask);
        colpart_kernel<<<grid_cp, blk256>>>(p_attnh);
        colfin_kernel<<<grid_cf, blk256>>>();
        gemm128<<<grid_g128, blk256>>>(wv + (size_t)i * CC * CC, p_h, nullptr, bv + (size_t)i * CC, nullptr, p_xvh);
        apply_hmma<<<grid_ap, blk256>>>(p_xvh, p_attnh, p_xr);
        gemm128<<<grid_g128, blk256>>>(wt + (size_t)i * CC * CC, p_h, p_xr, bt + (size_t)i * CC, p_y, nullptr);
        bn_part_kernel<<<grid_bp, blk256>>>(p_y);
        bn_finalize_kernel<<<1, CC>>>(sg + (size_t)i * CC, sb + (size_t)i * CC);
        bn_apply_kernel<<<grid_ba, blk256>>>(p_y, p_h, out, i);
    }
}

// round 5
// speedup vs baseline: 2.7887x; 1.0332x over previous
#include <cuda_runtime.h>
#include <cuda_fp16.h>
#include <cstdint>
#include <cstddef>

#define NN 4096
#define CC 128
#define BB 4
#define NEGV (-9e15f)

typedef unsigned long long ull;

// ---------------- scratch (device globals: no allocation allowed) -----------
__device__ float  g_h[(size_t)BB * CC * NN];                 // 8 MB
__device__ float  g_y[(size_t)BB * CC * NN];                 // 8 MB
__device__ __half g_qh[(size_t)BB * 32 * NN];                // 1 MB q hi [b][o][n]
__device__ __half g_ql[(size_t)BB * 32 * NN];                // 1 MB q lo
__device__ __half g_qth[(size_t)BB * NN * 32];               // 1 MB q hi transposed [b][n][o]
__device__ __half g_qtl[(size_t)BB * NN * 32];               // 1 MB q lo transposed
__device__ __half g_xvh[(size_t)BB * CC * NN];               // 4 MB value proj fp16
__device__ float  g_xr[(size_t)BB * CC * NN];                // 8 MB
__device__ float  g_attn[(size_t)BB * NN * NN];              // 256 MB energy fp32
__device__ __half g_attn_h[(size_t)BB * NN * NN];            // 128 MB attn fp16
__device__ float  g_colpart[(size_t)8 * BB * NN];
__device__ float  g_colinv[(size_t)BB * NN];
__device__ float  g_scale[CC];
__device__ float  g_shift[CC];
__device__ float  g_bnp1[8][CC];
__device__ float  g_bnp2[8][CC];

// ---------------- helpers ----------------------------------------------------
__device__ __forceinline__ float warp_red_sum(float v) {
#pragma unroll
    for (int o = 16; o > 0; o >>= 1) v += __shfl_xor_sync(0xffffffffu, v, o);
    return v;
}
__device__ __forceinline__ float warp_red_max(float v) {
#pragma unroll
    for (int o = 16; o > 0; o >>= 1) v = fmaxf(v, __shfl_xor_sync(0xffffffffu, v, o));
    return v;
}

__device__ __forceinline__ void fma2(ull& acc, ull a, ull b) {
    asm("fma.rn.f32x2 %0, %1, %2, %0;" : "+l"(acc) : "l"(a), "l"(b));
}
__device__ __forceinline__ ull pack2(float v) {
    ull r;
    unsigned u = __float_as_uint(v);
    asm("mov.b64 %0, {%1, %1};" : "=l"(r) : "r"(u));
    return r;
}
__device__ __forceinline__ float2 unpack2(ull v) {
    unsigned lo, hi;
    asm("mov.b64 {%0, %1}, %2;" : "=r"(lo), "=r"(hi) : "l"(v));
    return make_float2(__uint_as_float(lo), __uint_as_float(hi));
}

__device__ __forceinline__ void fma44(float acc[4][4], float4 w, float4 x) {
    acc[0][0] += w.x * x.x; acc[0][1] += w.x * x.y; acc[0][2] += w.x * x.z; acc[0][3] += w.x * x.w;
    acc[1][0] += w.y * x.x; acc[1][1] += w.y * x.y; acc[1][2] += w.y * x.z; acc[1][3] += w.y * x.w;
    acc[2][0] += w.z * x.x; acc[2][1] += w.z * x.y; acc[2][2] += w.z * x.z; acc[2][3] += w.z * x.w;
    acc[3][0] += w.w * x.x; acc[3][1] += w.w * x.y; acc[3][2] += w.w * x.z; acc[3][3] += w.w * x.w;
}

// 8x8 (8 rows x 4 pairs) FMA2 micro-step
__device__ __forceinline__ void microstep_8x8(
    ull acc[8][4], const float* __restrict__ rowS, const double* __restrict__ pairS,
    int tc, int tp)
{
    float4 xa = *(const float4*)&rowS[tc * 8];
    float4 xb = *(const float4*)&rowS[tc * 8 + 4];
    ull xc[8];
    xc[0] = pack2(xa.x); xc[1] = pack2(xa.y); xc[2] = pack2(xa.z); xc[3] = pack2(xa.w);
    xc[4] = pack2(xb.x); xc[5] = pack2(xb.y); xc[6] = pack2(xb.z); xc[7] = pack2(xb.w);
    ull af[4];
#pragma unroll
    for (int j = 0; j < 4; j++) af[j] = *(const ull*)&pairS[tp + 16 * j];
#pragma unroll
    for (int i = 0; i < 8; i++)
#pragma unroll
        for (int j = 0; j < 4; j++) fma2(acc[i][j], xc[i], af[j]);
}

// ---------------- HMMA helpers -------------------------------------------------
__device__ __forceinline__ void ldsm_x4(unsigned& r0, unsigned& r1, unsigned& r2, unsigned& r3,
                                        const void* p) {
    unsigned addr = (unsigned)__cvta_generic_to_shared(p);
    asm volatile("ldmatrix.sync.aligned.m8n8.x4.shared.b16 {%0,%1,%2,%3}, [%4];"
        : "=r"(r0), "=r"(r1), "=r"(r2), "=r"(r3) : "r"(addr));
}
__device__ __forceinline__ void ldsm_x4_t(unsigned& r0, unsigned& r1, unsigned& r2, unsigned& r3,
                                          const void* p) {
    unsigned addr = (unsigned)__cvta_generic_to_shared(p);
    asm volatile("ldmatrix.sync.aligned.m8n8.x4.trans.shared.b16 {%0,%1,%2,%3}, [%4];"
        : "=r"(r0), "=r"(r1), "=r"(r2), "=r"(r3) : "r"(addr));
}
__device__ __forceinline__ void mma16816(float d[4], const unsigned a[4], const unsigned b[2]) {
    asm volatile("mma.sync.aligned.m16n8k16.row.col.f32.f16.f16.f32 "
        "{%0,%1,%2,%3}, {%4,%5,%6,%7}, {%8,%9}, {%0,%1,%2,%3};"
        : "+f"(d[0]), "+f"(d[1]), "+f"(d[2]), "+f"(d[3])
        : "r"(a[0]), "r"(a[1]), "r"(a[2]), "r"(a[3]), "r"(b[0]), "r"(b[1]));
}

// ---------------- gemm_qk: q = Wqk (32xC) * X; writes fp16 hi/lo + transposed --
__global__ __launch_bounds__(256) void gemm_qk(
    const float* __restrict__ W, const float* __restrict__ X,
    __half* __restrict__ QH, __half* __restrict__ QL,
    __half* __restrict__ QTH, __half* __restrict__ QTL)
{
    __shared__ float Ws[CC][32];
    __shared__ float Xs[64][128];

    const int b  = blockIdx.z;
    const int n0 = blockIdx.x * 128;
    const int tid = threadIdx.x;

    for (int idx = tid; idx < 32 * CC; idx += 256) {
        int o = idx / CC, c = idx % CC;
        Ws[c][o] = W[(size_t)o * CC + c];
    }

    const float* x1 = X + (size_t)b * CC * NN;

    float acc[4][4] = {};
    const int to = tid / 32, tn = tid % 32;   // o-group 0..7, n-group 0..31

    for (int c0 = 0; c0 < CC; c0 += 64) {
        __syncthreads();
        for (int idx = tid; idx < 64 * 128; idx += 256) {
            int c = idx / 128, n = idx % 128;
            Xs[c][n] = x1[(size_t)(c0 + c) * NN + n0 + n];
        }
        __syncthreads();
#pragma unroll 8
        for (int c = 0; c < 64; c++) {
            float4 w = *(const float4*)&Ws[c0 + c][to * 4];
            float4 x = *(const float4*)&Xs[c][tn * 4];
            fma44(acc, w, x);
        }
    }

    __half h[4][4], l[4][4];
#pragma unroll
    for (int i = 0; i < 4; i++)
#pragma unroll
        for (int j = 0; j < 4; j++) {
            h[i][j] = __float2half_rn(acc[i][j]);
            l[i][j] = __float2half_rn(acc[i][j] - __half2float(h[i][j]));
        }

    // normal layout [o][n]
#pragma unroll
    for (int i = 0; i < 4; i++) {
        int o = to * 4 + i;
        size_t off = ((size_t)b * 32 + o) * NN + n0 + tn * 4;
        __half2 h0 = __halves2half2(h[i][0], h[i][1]);
        __half2 h1 = __halves2half2(h[i][2], h[i][3]);
        uint2 pk; pk.x = *(unsigned*)&h0; pk.y = *(unsigned*)&h1;
        *(uint2*)&QH[off] = pk;
        __half2 l0 = __halves2half2(l[i][0], l[i][1]);
        __half2 l1 = __halves2half2(l[i][2], l[i][3]);
        uint2 pl; pl.x = *(unsigned*)&l0; pl.y = *(unsigned*)&l1;
        *(uint2*)&QL[off] = pl;
    }
    // transposed layout [n][o]
#pragma unroll
    for (int j = 0; j < 4; j++) {
        int n = n0 + tn * 4 + j;
        size_t off = ((size_t)b * NN + n) * 32 + to * 4;
        __half2 h0 = __halves2half2(h[0][j], h[1][j]);
        __half2 h1 = __halves2half2(h[2][j], h[3][j]);
        uint2 pk; pk.x = *(unsigned*)&h0; pk.y = *(unsigned*)&h1;
        *(uint2*)&QTH[off] = pk;
        __half2 l0 = __halves2half2(l[0][j], l[1][j]);
        __half2 l1 = __halves2half2(l[2][j], l[3][j]);
        uint2 pl; pl.x = *(unsigned*)&l0; pl.y = *(unsigned*)&l1;
        *(uint2*)&QTL[off] = pl;
    }
}

// ---------------- gemm128: Y[b,o,n] = sum_c W[o,c]*(X1-X2)[b,c,n] + bias ------
__global__ __launch_bounds__(256, 2) void gemm128(
    const float* __restrict__ W, const float* __restrict__ X1,
    const float* __restrict__ X2, const float* __restrict__ bias,
    float* __restrict__ Y, __half* __restrict__ Yh)
{
    __shared__ float  Ws[32][132];
    __shared__ double Xd[32][66];

    const int b  = blockIdx.y;
    const int n0 = blockIdx.x * 128;
    const int tid = threadIdx.x;
    const int tp = tid & 15;
    const int tc = tid >> 4;

    const float* x1 = X1 + (size_t)b * CC * NN;
    const float* x2 = X2 ? X2 + (size_t)b * CC * NN : nullptr;

    ull acc[8][4];
#pragma unroll
    for (int i = 0; i < 8; i++)
#pragma unroll
        for (int j = 0; j < 4; j++) acc[i][j] = 0ull;

    for (int c0 = 0; c0 < CC; c0 += 32) {
        {
            int o = tid & 127, h = tid >> 7;
            const float* wsrc = W + (size_t)o * CC + c0 + h * 16;
            float4 wv[4];
#pragma unroll
            for (int r = 0; r < 4; r++) wv[r] = *(const float4*)&wsrc[r * 4];
#pragma unroll
            for (int r = 0; r < 4; r++) {
                int cbase = h * 16 + r * 4;
                Ws[cbase + 0][o] = wv[r].x;
                Ws[cbase + 1][o] = wv[r].y;
                Ws[cbase + 2][o] = wv[r].z;
                Ws[cbase + 3][o] = wv[r].w;
            }
        }
#pragma unroll
        for (int t = 0; t < 4; t++) {
            int idx = tid + t * 256;
            int c = idx >> 5, q = idx & 31;
            float4 v = *(const float4*)&x1[(size_t)(c0 + c) * NN + n0 + q * 4];
            if (x2) {
                float4 w = *(const float4*)&x2[(size_t)(c0 + c) * NN + n0 + q * 4];
                v.x -= w.x; v.y -= w.y; v.z -= w.z; v.w -= w.w;
            }
            *(double2*)&Xd[c][q * 2] = *(const double2*)&v;
        }
        __syncthreads();
#pragma unroll
        for (int k = 0; k < 32; k++)
            microstep_8x8(acc, &Ws[k][0], &Xd[k][0], tc, tp);
        __syncthreads();
    }

#pragma unroll
    for (int i = 0; i < 8; i++) {
        int o = tc * 8 + i;
        float bi = bias ? bias[o] : 0.f;
#pragma unroll
        for (int j = 0; j < 4; j++) {
            float2 r = unpack2(acc[i][j]);
            r.x += bi; r.y += bi;
            size_t off = ((size_t)b * CC + o) * NN + n0 + 2 * (tp + 16 * j);
            if (Yh) {
                *(__half2*)&Yh[off] = __floats2half2_rn(r.x, r.y);
            } else {
                *(float2*)&Y[off] = r;
            }
        }
    }
}

// ---------------- energy via HMMA hi/lo: E[n,m] = sum_o q[o,n]q[o,m] (fp32 out)
// 256 thr = 8 warps (2n x 4m), block tile 64n x 128m, K=32.
__global__ __launch_bounds__(256, 2) void energy_hmma(
    const __half* __restrict__ QH, const __half* __restrict__ QL,
    const __half* __restrict__ QTH, const __half* __restrict__ QTL,
    float* __restrict__ E)
{
    __shared__ __half Ah[64][40];
    __shared__ __half Al[64][40];
    __shared__ __half Bh[32][136];
    __shared__ __half Bl[32][136];

    const int b  = blockIdx.z;
    const int n0 = blockIdx.y * 64;
    const int m0 = blockIdx.x * 128;
    const int tid = threadIdx.x;
    const int wid = tid >> 5, lane = tid & 31;
    const int wn = wid & 1, wm = wid >> 1;

    // fill A (transposed q, [n][o]): 64 rows x 4 uint4
    {
        int r = tid >> 2, s = tid & 3;
        size_t off = ((size_t)b * NN + n0 + r) * 32 + s * 8;
        *(uint4*)&Ah[r][s * 8] = *(const uint4*)&QTH[off];
        *(uint4*)&Al[r][s * 8] = *(const uint4*)&QTL[off];
    }
    // fill B ([o][m]): 32 rows x 16 uint4
#pragma unroll
    for (int u = 0; u < 2; u++) {
        int idx = tid + u * 256;
        int r = idx >> 4, s = idx & 15;
        size_t off = ((size_t)b * 32 + r) * NN + m0 + s * 8;
        *(uint4*)&Bh[r][s * 8] = *(const uint4*)&QH[off];
        *(uint4*)&Bl[r][s * 8] = *(const uint4*)&QL[off];
    }
    __syncthreads();

    float acc[2][4][4];
#pragma unroll
    for (int i = 0; i < 2; i++)
#pragma unroll
        for (int j = 0; j < 4; j++)
#pragma unroll
            for (int k = 0; k < 4; k++) acc[i][j][k] = 0.f;

    const int lrow = (lane & 7) + ((lane >> 3) & 1) * 8;
    const int lsel = lane >> 4;
    const int g = lane >> 3;

#pragma unroll
    for (int kk = 0; kk < 2; kk++) {
        unsigned ah[2][4], al[2][4];
#pragma unroll
        for (int ci = 0; ci < 2; ci++) {
            ldsm_x4(ah[ci][0], ah[ci][1], ah[ci][2], ah[ci][3],
                    &Ah[wn * 32 + ci * 16 + lrow][kk * 16 + lsel * 8]);
            ldsm_x4(al[ci][0], al[ci][1], al[ci][2], al[ci][3],
                    &Al[wn * 32 + ci * 16 + lrow][kk * 16 + lsel * 8]);
        }
        unsigned bh[4][2], bl[4][2];
#pragma unroll
        for (int h = 0; h < 2; h++) {
            unsigned t0, t1, t2, t3;
            ldsm_x4_t(t0, t1, t2, t3,
                      &Bh[kk * 16 + (g & 1) * 8 + (lane & 7)][wm * 32 + h * 16 + (g >> 1) * 8]);
            bh[h * 2 + 0][0] = t0; bh[h * 2 + 0][1] = t1;
            bh[h * 2 + 1][0] = t2; bh[h * 2 + 1][1] = t3;
            ldsm_x4_t(t0, t1, t2, t3,
                      &Bl[kk * 16 + (g & 1) * 8 + (lane & 7)][wm * 32 + h * 16 + (g >> 1) * 8]);
            bl[h * 2 + 0][0] = t0; bl[h * 2 + 0][1] = t1;
            bl[h * 2 + 1][0] = t2; bl[h * 2 + 1][1] = t3;
        }
#pragma unroll
        for (int ci = 0; ci < 2; ci++)
#pragma unroll
            for (int nf = 0; nf < 4; nf++) {
                mma16816(acc[ci][nf], ah[ci], bh[nf]);   // hi*hi
                mma16816(acc[ci][nf], ah[ci], bl[nf]);   // hi*lo
                mma16816(acc[ci][nf], al[ci], bh[nf]);   // lo*hi
            }
    }

    const int r0l = lane >> 2, c0l = (lane & 3) * 2;
#pragma unroll
    for (int ci = 0; ci < 2; ci++) {
#pragma unroll
        for (int nf = 0; nf < 4; nf++) {
            int n = n0 + wn * 32 + ci * 16 + r0l;
            int mm = m0 + wm * 32 + nf * 8 + c0l;
            *(float2*)&E[((size_t)b * NN + n) * NN + mm] =
                make_float2(acc[ci][nf][0], acc[ci][nf][1]);
            *(float2*)&E[((size_t)b * NN + n + 8) * NN + mm] =
                make_float2(acc[ci][nf][2], acc[ci][nf][3]);
        }
    }
}

// ---------------- masked row softmax: fp32 energy in -> fp16 attn out ----------
__global__ __launch_bounds__(256) void softmax_kernel(
    const float* __restrict__ E, __half* __restrict__ AH, const int* __restrict__ mask)
{
    const int b = blockIdx.y, n = blockIdx.x;
    const float* row = E + ((size_t)b * NN + n) * NN;
    __half* rowh = AH + ((size_t)b * NN + n) * NN;
    const int* mrow = mask + (size_t)b * NN;
    const int tid = threadIdx.x;
    const int rm = mrow[n];

    float vals[16];
    float vmax = -3.4e38f;
#pragma unroll
    for (int k = 0; k < 4; k++) {
        int j = k * 1024 + tid * 4;
        float4 e = *(const float4*)&row[j];
        int4 mm = *(const int4*)&mrow[j];
        vals[k * 4 + 0] = (rm && mm.x) ? e.x : NEGV;
        vals[k * 4 + 1] = (rm && mm.y) ? e.y : NEGV;
        vals[k * 4 + 2] = (rm && mm.z) ? e.z : NEGV;
        vals[k * 4 + 3] = (rm && mm.w) ? e.w : NEGV;
        vmax = fmaxf(vmax, fmaxf(fmaxf(vals[k*4+0], vals[k*4+1]), fmaxf(vals[k*4+2], vals[k*4+3])));
    }

    __shared__ float rmx[8], rsm[8];
    float wm = warp_red_max(vmax);
    if ((tid & 31) == 0) rmx[tid >> 5] = wm;
    __syncthreads();
    float m8 = rmx[0];
#pragma unroll
    for (int i = 1; i < 8; i++) m8 = fmaxf(m8, rmx[i]);

    float s = 0.f;
#pragma unroll
    for (int i = 0; i < 16; i++) { vals[i] = __expf(vals[i] - m8); s += vals[i]; }
    float ws = warp_red_sum(s);
    if ((tid & 31) == 0) rsm[tid >> 5] = ws;
    __syncthreads();
    float tot = 0.f;
#pragma unroll
    for (int i = 0; i < 8; i++) tot += rsm[i];
    float inv = 1.f / tot;

#pragma unroll
    for (int k = 0; k < 4; k++) {
        int j = k * 1024 + tid * 4;
        __half2 h0 = __floats2half2_rn(vals[k*4+0]*inv, vals[k*4+1]*inv);
        __half2 h1 = __floats2half2_rn(vals[k*4+2]*inv, vals[k*4+3]*inv);
        uint2 pk;
        pk.x = *(unsigned*)&h0;
        pk.y = *(unsigned*)&h1;
        *(uint2*)&rowh[j] = pk;
    }
}

// ---------------- column-sum (fp16 attn, split over n) -------------------------
__global__ __launch_bounds__(256) void colpart_kernel(const __half* __restrict__ AH)
{
    const int b = blockIdx.z;
    const int split = blockIdx.y;
    const int m2 = blockIdx.x * 256 + threadIdx.x;
    const __half2* a = (const __half2*)(AH + (size_t)b * NN * NN) + m2;
    const int nbeg = split * 512;
    float2 s0 = make_float2(0.f, 0.f), s1 = make_float2(0.f, 0.f);
#pragma unroll 4
    for (int n = nbeg; n < nbeg + 512; n += 2) {
        float2 f0 = __half22float2(a[(size_t)(n + 0) * (NN / 2)]);
        float2 f1 = __half22float2(a[(size_t)(n + 1) * (NN / 2)]);
        s0.x += f0.x; s0.y += f0.y;
        s1.x += f1.x; s1.y += f1.y;
    }
    float2 r = make_float2(s0.x + s1.x, s0.y + s1.y);
    *(float2*)&g_colpart[((size_t)split * BB + b) * NN + 2 * m2] = r;
}

__global__ __launch_bounds__(256) void colfin_kernel()
{
    const int b = blockIdx.y;
    const int m = blockIdx.x * 256 + threadIdx.x;
    float s = 0.f;
#pragma unroll
    for (int split = 0; split < 8; split++)
        s += g_colpart[((size_t)split * BB + b) * NN + m];
    g_colinv[(size_t)b * NN + m] = 1.f / (1e-9f + s);
}

// ---------------- attn apply via HMMA: XR[b,c,m] = (sum_n XV*A)*colinv[m] ------
// 256 threads = 8 warps (4c x 2m), block tile 128c x 64m: attn read ONCE.
__global__ __launch_bounds__(256, 2) void apply_hmma(
    const __half* __restrict__ XVH, const __half* __restrict__ AH,
    float* __restrict__ XR)
{
    __shared__ __half XVs[128][72];   // [c][k]
    __shared__ __half As[64][72];     // [k][m]

    const int b  = blockIdx.y;
    const int m0 = blockIdx.x * 64;
    const int tid = threadIdx.x;
    const int wid = tid >> 5, lane = tid & 31;
    const int wc = wid & 3, wm = wid >> 2;

    const __half* xv = XVH + (size_t)b * CC * NN;
    const __half* at = AH + (size_t)b * NN * NN;

    float acc[2][4][4];
#pragma unroll
    for (int i = 0; i < 2; i++)
#pragma unroll
        for (int j = 0; j < 4; j++)
#pragma unroll
            for (int k = 0; k < 4; k++) acc[i][j][k] = 0.f;

    const int lrow = (lane & 7) + ((lane >> 3) & 1) * 8;
    const int lsel = lane >> 4;
    const int g = lane >> 3;

    for (int k0 = 0; k0 < NN; k0 += 64) {
#pragma unroll
        for (int u = 0; u < 4; u++) {
            int idx = tid + u * 256;
            int r = idx >> 3, s = idx & 7;
            *(uint4*)&XVs[r][s * 8] = *(const uint4*)&xv[(size_t)r * NN + k0 + s * 8];
        }
#pragma unroll
        for (int u = 0; u < 2; u++) {
            int idx = tid + u * 256;
            int r = idx >> 3, s = idx & 7;
            *(uint4*)&As[r][s * 8] = *(const uint4*)&at[(size_t)(k0 + r) * NN + m0 + s * 8];
        }
        __syncthreads();

#pragma unroll
        for (int kk = 0; kk < 4; kk++) {
            unsigned a[2][4];
#pragma unroll
            for (int ci = 0; ci < 2; ci++)
                ldsm_x4(a[ci][0], a[ci][1], a[ci][2], a[ci][3],
                        &XVs[wc * 32 + ci * 16 + lrow][kk * 16 + lsel * 8]);
            unsigned bf[4][2];
#pragma unroll
            for (int h = 0; h < 2; h++) {
                unsigned t0, t1, t2, t3;
                ldsm_x4_t(t0, t1, t2, t3,
                          &As[kk * 16 + (g & 1) * 8 + (lane & 7)][wm * 32 + h * 16 + (g >> 1) * 8]);
                bf[h * 2 + 0][0] = t0; bf[h * 2 + 0][1] = t1;
                bf[h * 2 + 1][0] = t2; bf[h * 2 + 1][1] = t3;
            }
#pragma unroll
            for (int ci = 0; ci < 2; ci++)
#pragma unroll
                for (int nf = 0; nf < 4; nf++)
                    mma16816(acc[ci][nf], a[ci], bf[nf]);
        }
        __syncthreads();
    }

    const float* cinv = g_colinv + (size_t)b * NN + m0;
    const int r0l = lane >> 2, c0l = (lane & 3) * 2;
#pragma unroll
    for (int ci = 0; ci < 2; ci++) {
#pragma unroll
        for (int nf = 0; nf < 4; nf++) {
            int c = wc * 32 + ci * 16 + r0l;
            int mm = wm * 32 + nf * 8 + c0l;
            float2 cv = *(const float2*)&cinv[mm];
            float2 lo = make_float2(acc[ci][nf][0] * cv.x, acc[ci][nf][1] * cv.y);
            *(float2*)&XR[((size_t)b * CC + c) * NN + m0 + mm] = lo;
            float2 hi = make_float2(acc[ci][nf][2] * cv.x, acc[ci][nf][3] * cv.y);
            *(float2*)&XR[((size_t)b * CC + c + 8) * NN + m0 + mm] = hi;
        }
    }
}

// ---------------- BN stats: 8-way partials + finalize ---------------------------
__global__ __launch_bounds__(256) void bn_part_kernel(const float* __restrict__ Y)
{
    const int c = blockIdx.x;
    const int s = blockIdx.y;
    const int b = s >> 1;
    const int n0 = (s & 1) * 2048;
    const float* p = Y + ((size_t)b * CC + c) * NN + n0;
    const int tid = threadIdx.x;
    float sum = 0.f, sq = 0.f;
#pragma unroll
    for (int i = 0; i < 8; i++) {
        float v = p[tid + i * 256];
        sum += v; sq += v * v;
    }
    sum = warp_red_sum(sum); sq = warp_red_sum(sq);
    __shared__ float r1[8], r2[8];
    if ((tid & 31) == 0) { r1[tid >> 5] = sum; r2[tid >> 5] = sq; }
    __syncthreads();
    if (tid == 0) {
        float ts = 0.f, t2 = 0.f;
#pragma unroll
        for (int i = 0; i < 8; i++) { ts += r1[i]; t2 += r2[i]; }
        g_bnp1[s][c] = ts;
        g_bnp2[s][c] = t2;
    }
}

__global__ void bn_finalize_kernel(const float* __restrict__ gam, const float* __restrict__ bet)
{
    const int c = threadIdx.x;
    float ts = 0.f, t2 = 0.f;
#pragma unroll
    for (int s = 0; s < 8; s++) { ts += g_bnp1[s][c]; t2 += g_bnp2[s][c]; }
    const float invN = 1.f / (float)(BB * NN);
    float mean = ts * invN;
    float var  = t2 * invN - mean * mean;
    float sc = gam[c] * rsqrtf(var + 1e-5f);
    g_scale[c] = sc;
    g_shift[c] = bet[c] - mean * sc;
}

// ---------------- BN apply (+relu) [+residual into h and output slab] -----------
__global__ __launch_bounds__(256) void bn_apply_kernel(
    const float* __restrict__ Y, float* __restrict__ H,
    float* __restrict__ OUT, int layer)
{
    size_t f = ((size_t)blockIdx.x * 256 + threadIdx.x) * 4;
    int n = (int)(f % NN);
    int c = (int)((f / NN) % CC);
    int b = (int)(f / ((size_t)NN * CC));
    float sc = g_scale[c], sh = g_shift[c];
    float4 y = *(const float4*)&Y[f];
    float4 r;
    r.x = fmaxf(fmaf(y.x, sc, sh), 0.f);
    r.y = fmaxf(fmaf(y.y, sc, sh), 0.f);
    r.z = fmaxf(fmaf(y.z, sc, sh), 0.f);
    r.w = fmaxf(fmaf(y.w, sc, sh), 0.f);
    if (OUT) {
        float4 h = *(const float4*)&H[f];
        r.x += h.x; r.y += h.y; r.z += h.z; r.w += h.w;
        *(float4*)&H[f] = r;
        *(float4*)&OUT[(((size_t)b * 4 * CC) + (size_t)layer * CC + c) * NN + n] = r;
    } else {
        *(float4*)&H[f] = r;
    }
}

// ---------------- launch ---------------------------------------------------------
extern "C" void kernel_launch(void* const* d_in, const int* in_sizes, int n_in,
                              void* d_out, int out_size)
{
    const float* x    = (const float*)d_in[0];
    const int*   mask = (const int*)  d_in[1];
    const float* w1   = (const float*)d_in[2];
    const float* g1   = (const float*)d_in[3];
    const float* b1   = (const float*)d_in[4];
    const float* w2   = (const float*)d_in[5];
    const float* g2   = (const float*)d_in[6];
    const float* b2   = (const float*)d_in[7];
    const float* wqk  = (const float*)d_in[8];
    const float* wv   = (const float*)d_in[9];
    const float* bv   = (const float*)d_in[10];
    const float* wt   = (const float*)d_in[11];
    const float* bt   = (const float*)d_in[12];
    const float* sg   = (const float*)d_in[13];
    const float* sb   = (const float*)d_in[14];
    float* out = (float*)d_out;

    float *p_h, *p_y, *p_xr, *p_attn;
    __half *p_xvh, *p_attnh, *p_qh, *p_ql, *p_qth, *p_qtl;
    cudaGetSymbolAddress((void**)&p_h,     g_h);
    cudaGetSymbolAddress((void**)&p_y,     g_y);
    cudaGetSymbolAddress((void**)&p_xvh,   g_xvh);
    cudaGetSymbolAddress((void**)&p_xr,    g_xr);
    cudaGetSymbolAddress((void**)&p_attn,  g_attn);
    cudaGetSymbolAddress((void**)&p_attnh, g_attn_h);
    cudaGetSymbolAddress((void**)&p_qh,    g_qh);
    cudaGetSymbolAddress((void**)&p_ql,    g_ql);
    cudaGetSymbolAddress((void**)&p_qth,   g_qth);
    cudaGetSymbolAddress((void**)&p_qtl,   g_qtl);

    const dim3 blk256(256);
    const dim3 grid_g128(NN / 128, BB);
    const dim3 grid_qk(NN / 128, 1, BB);
    const dim3 grid_e(NN / 128, NN / 64, BB);
    const dim3 grid_sm(NN, BB);
    const dim3 grid_cp(NN / 512, 8, BB);
    const dim3 grid_cf(NN / 256, BB);
    const dim3 grid_ap(NN / 64, BB);
    const dim3 grid_bp(CC, 8);
    const dim3 grid_ba((unsigned)(((size_t)BB * CC * NN / 4) / 256));

    // head: two conv+BN+relu
    gemm128<<<grid_g128, blk256>>>(w1, x, nullptr, nullptr, p_y, nullptr);
    bn_part_kernel<<<grid_bp, blk256>>>(p_y);
    bn_finalize_kernel<<<1, CC>>>(g1, b1);
    bn_apply_kernel<<<grid_ba, blk256>>>(p_y, p_h, nullptr, 0);

    gemm128<<<grid_g128, blk256>>>(w2, p_h, nullptr, nullptr, p_y, nullptr);
    bn_part_kernel<<<grid_bp, blk256>>>(p_y);
    bn_finalize_kernel<<<1, CC>>>(g2, b2);
    bn_apply_kernel<<<grid_ba, blk256>>>(p_y, p_h, nullptr, 0);

    // 4 offset-attention layers
    for (int i = 0; i < 4; i++) {
        gemm_qk<<<grid_qk, blk256>>>(wqk + (size_t)i * 32 * CC, p_h, p_qh, p_ql, p_qth, p_qtl);
        energy_hmma<<<grid_e, blk256>>>(p_qh, p_ql, p_qth, p_qtl, p_attn);
        softmax_kernel<<<grid_sm, blk256>>>(p_attn, p_attnh, mask);
        colpart_kernel<<<grid_cp, blk256>>>(p_attnh);
        colfin_kernel<<<grid_cf, blk256>>>();
        gemm128<<<grid_g128, blk256>>>(wv + (size_t)i * CC * CC, p_h, nullptr, bv + (size_t)i * CC, nullptr, p_xvh);
        apply_hmma<<<grid_ap, blk256>>>(p_xvh, p_attnh, p_xr);
        gemm128<<<grid_g128, blk256>>>(wt + (size_t)i * CC * CC, p_h, p_xr, bt + (size_t)i * CC, p_y, nullptr);
        bn_part_kernel<<<grid_bp, blk256>>>(p_y);
        bn_finalize_kernel<<<1, CC>>>(sg + (size_t)i * CC, sb + (size_t)i * CC);
        bn_apply_kernel<<<grid_ba, blk256>>>(p_y, p_h, out, i);
    }
}